// round 5
// baseline (speedup 1.0000x reference)
#include <cuda_runtime.h>
#include <cstdint>
#include <math.h>

// ---------------- model constants ----------------
#define C_DIM   1024
#define H_NUM   16
#define D_HEAD  64
#define L_NUM   8
#define T_SEQ   1024
#define B_SZ    2
#define M_ROWS  (B_SZ * T_SEQ)      // 2048
#define FF_DIM  4096
#define V_SZ    32000

// ---------------- device scratch ----------------
__device__ __align__(256) float g_x   [M_ROWS * C_DIM];
__device__ __align__(256) float g_h   [M_ROWS * C_DIM];
__device__ __align__(256) float g_qkv [M_ROWS * 3 * C_DIM];
__device__ __align__(256) float g_ff  [M_ROWS * FF_DIM];
__device__ __align__(256) float g_wp  [C_DIM * 3 * C_DIM];   // packed qkv weights [C, 3C] (KN)

// ============================================================
// helpers
// ============================================================
__device__ __forceinline__ uint32_t smem_u32(const void* p) {
    uint32_t a;
    asm("{ .reg .u64 t; cvta.to.shared.u64 t, %1; cvt.u32.u64 %0, t; }" : "=r"(a) : "l"(p));
    return a;
}
__device__ __forceinline__ void cpa16(uint32_t dst, const float* src) {
    asm volatile("cp.async.cg.shared.global [%0], [%1], 16;" :: "r"(dst), "l"(src));
}
__device__ __forceinline__ uint32_t f2tf32(float x) {
    uint32_t r;
    asm("cvt.rna.tf32.f32 %0, %1;" : "=r"(r) : "f"(x));
    return r;
}
__device__ __forceinline__ float tf32r(float x) { return __uint_as_float(f2tf32(x)); }
__device__ __forceinline__ void mma_tf32(float& c0, float& c1, float& c2, float& c3,
                                         uint32_t a0, uint32_t a1, uint32_t a2, uint32_t a3,
                                         uint32_t b0, uint32_t b1) {
    asm volatile("mma.sync.aligned.m16n8k8.row.col.f32.tf32.tf32.f32 "
        "{%0,%1,%2,%3}, {%4,%5,%6,%7}, {%8,%9}, {%0,%1,%2,%3};"
        : "+f"(c0), "+f"(c1), "+f"(c2), "+f"(c3)
        : "r"(a0), "r"(a1), "r"(a2), "r"(a3), "r"(b0), "r"(b1));
}

// ============================================================
// TF32 mma.sync GEMM, CTA tile 128x128, BK=32, 2-stage cp.async,
// 8 warps (2x4), warp tile 64x32.
//   BNK=0: B stored [K, N] row-major (natural weight layout)
//   BNK=1: B stored [N, K] row-major (A @ B^T, used for logits)
//   CVTB : cvt.rna.tf32 applied to B fragments at load (raw fp32 weights)
// A is always [M, K], assumed pre-rounded to TF32.
// ============================================================
#define ROWA        36
#define A_TILE_F    (128 * ROWA)                 // 4608
#define ROWB_KN     132
#define B_TILE_KN_F (32 * ROWB_KN)               // 4224
#define STAGE_KN_F  (A_TILE_F + B_TILE_KN_F)     // 8832
#define GSM_KN      (2 * STAGE_KN_F * 4)         // 70656
#define STAGE_NK_F  (2 * A_TILE_F)               // 9216
#define GSM_NK      (2 * STAGE_NK_F * 4)         // 73728

template<int BNK, int CVTB>
__global__ __launch_bounds__(256, 2)
void tgemm(const float* __restrict__ A, const float* __restrict__ B,
           float* __restrict__ Cmat, const float* __restrict__ bias,
           const float* __restrict__ res, int N, int K, int relu)
{
    constexpr int STAGE_F = BNK ? STAGE_NK_F : STAGE_KN_F;
    extern __shared__ float smf[];
    uint32_t sbase = smem_u32(smf);
    int tid  = threadIdx.x;
    int wid  = tid >> 5;
    int lane = tid & 31;
    int wm   = wid >> 2;          // 0..1
    int wn   = wid & 3;           // 0..3
    int bm = blockIdx.y << 7;
    int bn = blockIdx.x << 7;

    const float* Ag = A + (size_t)bm * K;
    const float* Bg;
    if (BNK) Bg = B + (size_t)bn * K;        // [N,K]: row = n
    else     Bg = B + bn;                    // [K,N]: col offset
    int NC = K >> 5;

    float acc[4][4][4];
#pragma unroll
    for (int mf = 0; mf < 4; mf++)
#pragma unroll
        for (int nf = 0; nf < 4; nf++)
#pragma unroll
            for (int k = 0; k < 4; k++) acc[mf][nf][k] = 0.f;

    // ---- tile loader ----
    auto load_tile = [&](int ch, int stage) {
        int k0 = ch << 5;
        uint32_t so = sbase + (uint32_t)(stage * STAGE_F) * 4u;
#pragma unroll
        for (int i = 0; i < 4; i++) {          // A: 128 rows x 32 cols
            int id = tid + (i << 8);
            int r = id >> 3, c = (id & 7) << 2;
            cpa16(so + ((uint32_t)(r * ROWA + c) << 2),
                  Ag + (size_t)r * K + k0 + c);
        }
        uint32_t bo = so + (uint32_t)A_TILE_F * 4u;
        if (BNK) {
#pragma unroll
            for (int i = 0; i < 4; i++) {      // B: 128 n-rows x 32 k-cols
                int id = tid + (i << 8);
                int r = id >> 3, c = (id & 7) << 2;
                cpa16(bo + ((uint32_t)(r * ROWA + c) << 2),
                      Bg + (size_t)r * K + k0 + c);
            }
        } else {
#pragma unroll
            for (int i = 0; i < 4; i++) {      // B: 32 k-rows x 128 n-cols
                int id = tid + (i << 8);
                int r = id >> 5, c = (id & 31) << 2;
                cpa16(bo + ((uint32_t)(r * ROWB_KN + c) << 2),
                      Bg + (size_t)(k0 + r) * N + c);
            }
        }
    };

    load_tile(0, 0);
    asm volatile("cp.async.commit_group;");

    for (int ch = 0; ch < NC; ch++) {
        if (ch > 0) __syncthreads();
        if (ch + 1 < NC) load_tile(ch + 1, (ch + 1) & 1);
        asm volatile("cp.async.commit_group;");
        asm volatile("cp.async.wait_group 1;");
        __syncthreads();

        const float* sA = smf + (ch & 1) * STAGE_F;
        const float* sB = sA + A_TILE_F;
        int ar = (wm << 6) + (lane >> 2);
        int kc = lane & 3;
#pragma unroll
        for (int ks = 0; ks < 4; ks++) {
            int k8 = (ks << 3) + kc;
            uint32_t af[4][4], bf[4][2];
#pragma unroll
            for (int mf = 0; mf < 4; mf++) {
                const float* p = sA + (ar + (mf << 4)) * ROWA + k8;
                af[mf][0] = __float_as_uint(p[0]);
                af[mf][1] = __float_as_uint(p[8 * ROWA]);
                af[mf][2] = __float_as_uint(p[4]);
                af[mf][3] = __float_as_uint(p[8 * ROWA + 4]);
            }
            if (BNK) {
                int bc = (wn << 5) + (lane >> 2);
#pragma unroll
                for (int nf = 0; nf < 4; nf++) {
                    const float* p = sB + (bc + (nf << 3)) * ROWA + k8;
                    if (CVTB) { bf[nf][0] = f2tf32(p[0]); bf[nf][1] = f2tf32(p[4]); }
                    else      { bf[nf][0] = __float_as_uint(p[0]); bf[nf][1] = __float_as_uint(p[4]); }
                }
            } else {
                int nc = (wn << 5) + (lane >> 2);
#pragma unroll
                for (int nf = 0; nf < 4; nf++) {
                    const float* p = sB + k8 * ROWB_KN + nc + (nf << 3);
                    if (CVTB) { bf[nf][0] = f2tf32(p[0]); bf[nf][1] = f2tf32(p[4 * ROWB_KN]); }
                    else      { bf[nf][0] = __float_as_uint(p[0]); bf[nf][1] = __float_as_uint(p[4 * ROWB_KN]); }
                }
            }
#pragma unroll
            for (int mf = 0; mf < 4; mf++)
#pragma unroll
                for (int nf = 0; nf < 4; nf++)
                    mma_tf32(acc[mf][nf][0], acc[mf][nf][1], acc[mf][nf][2], acc[mf][nf][3],
                             af[mf][0], af[mf][1], af[mf][2], af[mf][3],
                             bf[nf][0], bf[nf][1]);
        }
    }

    // ---- epilogue ----
    int row0 = bm + (wm << 6) + (lane >> 2);
    int col0 = bn + (wn << 5) + ((lane & 3) << 1);
#pragma unroll
    for (int mf = 0; mf < 4; mf++) {
#pragma unroll
        for (int half = 0; half < 2; half++) {
            int row = row0 + (mf << 4) + half * 8;
            float* op = Cmat + (size_t)row * N + col0;
            const float* rp = res ? res + (size_t)row * N + col0 : nullptr;
#pragma unroll
            for (int nf = 0; nf < 4; nf++) {
                float2 v;
                v.x = acc[mf][nf][half * 2 + 0];
                v.y = acc[mf][nf][half * 2 + 1];
                int c = (nf << 3);
                if (bias) {
                    v.x += bias[col0 + c];
                    v.y += bias[col0 + c + 1];
                }
                if (relu) {   // feeds next GEMM's A: pre-round to TF32
                    v.x = tf32r(fmaxf(v.x, 0.f));
                    v.y = tf32r(fmaxf(v.y, 0.f));
                }
                if (rp) {
                    float2 r2 = *(const float2*)(rp + c);
                    v.x += r2.x; v.y += r2.y;
                }
                *(float2*)(op + c) = v;
            }
        }
    }
}

// ---------------- embedding ----------------
__global__ void k_embed(const int* __restrict__ idx,
                        const float* __restrict__ tok,
                        const float* __restrict__ pos,
                        float* __restrict__ x)
{
    int m = blockIdx.x;
    int c = threadIdx.x * 4;
    int t = m & (T_SEQ - 1);
    int v = idx[m];
    float4 a = *(const float4*)(tok + (size_t)v * C_DIM + c);
    float4 p = *(const float4*)(pos + (size_t)t * C_DIM + c);
    a.x += p.x; a.y += p.y; a.z += p.z; a.w += p.w;
    *(float4*)(x + (size_t)m * C_DIM + c) = a;
}

// ---------------- layernorm (outputs pre-rounded to TF32) ----------------
__global__ void k_ln(const float* __restrict__ x,
                     const float* __restrict__ sc,
                     const float* __restrict__ bi,
                     float* __restrict__ out)
{
    int m = blockIdx.x;
    int tid = threadIdx.x;                 // 256 threads
    int c = tid * 4;
    float4 v = *(const float4*)(x + (size_t)m * C_DIM + c);
    float s = v.x + v.y + v.z + v.w;
    float q = v.x*v.x + v.y*v.y + v.z*v.z + v.w*v.w;

    __shared__ float rs[8], rq[8];
#pragma unroll
    for (int o = 16; o > 0; o >>= 1) {
        s += __shfl_xor_sync(0xffffffffu, s, o);
        q += __shfl_xor_sync(0xffffffffu, q, o);
    }
    if ((tid & 31) == 0) { rs[tid >> 5] = s; rq[tid >> 5] = q; }
    __syncthreads();
    float sum = 0.f, sq = 0.f;
#pragma unroll
    for (int w = 0; w < 8; w++) { sum += rs[w]; sq += rq[w]; }

    float mu = sum * (1.0f / C_DIM);
    float var = sq * (1.0f / C_DIM) - mu * mu;
    float rstd = rsqrtf(var + 1e-5f);

    float4 svv = *(const float4*)(sc + c);
    float4 bvv = *(const float4*)(bi + c);
    float4 o;
    o.x = tf32r((v.x - mu) * rstd * svv.x + bvv.x);
    o.y = tf32r((v.y - mu) * rstd * svv.y + bvv.y);
    o.z = tf32r((v.z - mu) * rstd * svv.z + bvv.z);
    o.w = tf32r((v.w - mu) * rstd * svv.w + bvv.w);
    *(float4*)(out + (size_t)m * C_DIM + c) = o;
}

// ---------------- pack qkv weights (L,H,C,D) -> [C, 3C] KN layout (TF32) ----------------
__global__ __launch_bounds__(256)
void k_packKN(const float* __restrict__ Wq, const float* __restrict__ Wk,
              const float* __restrict__ Wv, float* __restrict__ out, int l)
{
    int i = blockIdx.x * 256 + threadIdx.x;   // i = k*3072 + n
    int n = i % 3072;
    int k = i / 3072;
    int s = n >> 10;
    int r = n & 1023;
    int hh = r >> 6;
    int d = r & 63;
    const float* W = (s == 0) ? Wq : ((s == 1) ? Wk : Wv);
    out[i] = tf32r(W[(((size_t)l * H_NUM + hh) * C_DIM + k) * D_HEAD + d]);
}

// ---------------- causal flash attention (output pre-rounded) ----------------
__global__ __launch_bounds__(256)
void k_attn(const float* __restrict__ qkv, float* __restrict__ outb)
{
    __shared__ float qs[64][64];
    __shared__ float ks[32][65];
    __shared__ float vs[32][65];
    __shared__ float ps[64][33];

    int qt  = blockIdx.x;
    int b   = blockIdx.y >> 4;
    int hh  = blockIdx.y & 15;
    int tid = threadIdx.x;
    int tx  = tid & 15, ty = tid >> 4;

    const float* qbase = qkv + (size_t)(b * T_SEQ + qt * 64) * 3072 + hh * 64;
#pragma unroll
    for (int e = 0; e < 16; e++) {
        int i = tid + e * 256;
        int r = i >> 6, d = i & 63;
        qs[r][d] = qbase[(size_t)r * 3072 + d] * 0.125f;
    }

    float m_r[4], l_r[4], oa[4][4];
#pragma unroll
    for (int i = 0; i < 4; i++) {
        m_r[i] = -1e30f; l_r[i] = 0.f;
#pragma unroll
        for (int j = 0; j < 4; j++) oa[i][j] = 0.f;
    }

    const float* kb = qkv + (size_t)(b * T_SEQ) * 3072 + 1024 + hh * 64;
    const float* vb = qkv + (size_t)(b * T_SEQ) * 3072 + 2048 + hh * 64;

    int nkt = 2 * qt + 2;
    for (int kt = 0; kt < nkt; kt++) {
        __syncthreads();
#pragma unroll
        for (int e = 0; e < 8; e++) {
            int i = tid + e * 256;
            int r = i >> 6, d = i & 63;
            ks[r][d] = kb[(size_t)(kt * 32 + r) * 3072 + d];
            vs[r][d] = vb[(size_t)(kt * 32 + r) * 3072 + d];
        }
        __syncthreads();

        float sv[4][2];
#pragma unroll
        for (int i = 0; i < 4; i++) { sv[i][0] = 0.f; sv[i][1] = 0.f; }
#pragma unroll 8
        for (int d = 0; d < 64; d++) {
            float b0 = ks[2 * tx + 0][d];
            float b1 = ks[2 * tx + 1][d];
#pragma unroll
            for (int i = 0; i < 4; i++) {
                float a = qs[4 * ty + i][d];
                sv[i][0] += a * b0;
                sv[i][1] += a * b1;
            }
        }

        if (kt >= 2 * qt) {
#pragma unroll
            for (int i = 0; i < 4; i++)
#pragma unroll
                for (int j = 0; j < 2; j++) {
                    int sg = kt * 32 + 2 * tx + j;
                    int tg = qt * 64 + 4 * ty + i;
                    if (sg > tg) sv[i][j] = -1e30f;
                }
        }

#pragma unroll
        for (int i = 0; i < 4; i++) {
            float mloc = fmaxf(sv[i][0], sv[i][1]);
#pragma unroll
            for (int o = 8; o > 0; o >>= 1)
                mloc = fmaxf(mloc, __shfl_xor_sync(0xffffffffu, mloc, o));
            float mnew = fmaxf(m_r[i], mloc);
            float p0 = expf(sv[i][0] - mnew);
            float p1 = expf(sv[i][1] - mnew);
            float corr = expf(m_r[i] - mnew);
            float rsum = p0 + p1;
#pragma unroll
            for (int o = 8; o > 0; o >>= 1)
                rsum += __shfl_xor_sync(0xffffffffu, rsum, o);
            l_r[i] = l_r[i] * corr + rsum;
            m_r[i] = mnew;
            oa[i][0] *= corr; oa[i][1] *= corr; oa[i][2] *= corr; oa[i][3] *= corr;
            ps[4 * ty + i][2 * tx + 0] = p0;
            ps[4 * ty + i][2 * tx + 1] = p1;
        }
        __syncthreads();

#pragma unroll 4
        for (int s = 0; s < 32; s++) {
            float b0 = vs[s][4 * tx + 0];
            float b1 = vs[s][4 * tx + 1];
            float b2 = vs[s][4 * tx + 2];
            float b3 = vs[s][4 * tx + 3];
#pragma unroll
            for (int i = 0; i < 4; i++) {
                float a = ps[4 * ty + i][s];
                oa[i][0] += a * b0;
                oa[i][1] += a * b1;
                oa[i][2] += a * b2;
                oa[i][3] += a * b3;
            }
        }
    }

    float* ob = outb + (size_t)(b * T_SEQ + qt * 64) * C_DIM + hh * 64;
#pragma unroll
    for (int i = 0; i < 4; i++) {
        float inv = 1.0f / l_r[i];
#pragma unroll
        for (int j = 0; j < 4; j++)
            ob[(size_t)(4 * ty + i) * C_DIM + 4 * tx + j] = tf32r(oa[i][j] * inv);
    }
}

// ---------------- launcher ----------------
extern "C" void kernel_launch(void* const* d_in, const int* in_sizes, int n_in,
                              void* d_out, int out_size)
{
    const int*   idx    = (const int*)  d_in[0];
    const float* tok    = (const float*)d_in[1];
    const float* pos    = (const float*)d_in[2];
    const float* ln1_s  = (const float*)d_in[3];
    const float* ln1_b  = (const float*)d_in[4];
    const float* Wq     = (const float*)d_in[5];
    const float* Wk     = (const float*)d_in[6];
    const float* Wv     = (const float*)d_in[7];
    const float* Wo     = (const float*)d_in[8];
    const float* bo     = (const float*)d_in[9];
    const float* ln2_s  = (const float*)d_in[10];
    const float* ln2_b  = (const float*)d_in[11];
    const float* W1     = (const float*)d_in[12];
    const float* b1     = (const float*)d_in[13];
    const float* W2     = (const float*)d_in[14];
    const float* b2     = (const float*)d_in[15];
    const float* lnf_s  = (const float*)d_in[16];
    const float* lnf_b  = (const float*)d_in[17];
    float* out = (float*)d_out;

    float *x, *h, *qkv, *ff, *wp;
    cudaGetSymbolAddress((void**)&x,   g_x);
    cudaGetSymbolAddress((void**)&h,   g_h);
    cudaGetSymbolAddress((void**)&qkv, g_qkv);
    cudaGetSymbolAddress((void**)&ff,  g_ff);
    cudaGetSymbolAddress((void**)&wp,  g_wp);

    cudaFuncSetAttribute(tgemm<0,0>, cudaFuncAttributeMaxDynamicSharedMemorySize, GSM_KN);
    cudaFuncSetAttribute(tgemm<0,1>, cudaFuncAttributeMaxDynamicSharedMemorySize, GSM_KN);
    cudaFuncSetAttribute(tgemm<1,1>, cudaFuncAttributeMaxDynamicSharedMemorySize, GSM_NK);

    k_embed<<<M_ROWS, 256>>>(idx, tok, pos, x);

    for (int l = 0; l < L_NUM; l++) {
        // LN1
        k_ln<<<M_ROWS, 256>>>(x, ln1_s + l * C_DIM, ln1_b + l * C_DIM, h);
        // pack qkv weights [C, 3C] (TF32) for this layer
        k_packKN<<<(C_DIM * 3 * C_DIM) / 256, 256>>>(Wq, Wk, Wv, wp, l);
        // fused qkv GEMM: (2048,3072) = h @ wp
        tgemm<0,0><<<dim3(3072 / 128, M_ROWS / 128), 256, GSM_KN>>>(
            h, wp, qkv, nullptr, nullptr, 3072, C_DIM, 0);
        // attention -> h
        k_attn<<<dim3(T_SEQ / 64, B_SZ * H_NUM), 256>>>(qkv, h);
        // x = x + h @ Wo + bo   (Wo natural [C,C] KN)
        tgemm<0,1><<<dim3(C_DIM / 128, M_ROWS / 128), 256, GSM_KN>>>(
            h, Wo + (size_t)l * C_DIM * C_DIM, x, bo + l * C_DIM, x, C_DIM, C_DIM, 0);
        // LN2
        k_ln<<<M_ROWS, 256>>>(x, ln2_s + l * C_DIM, ln2_b + l * C_DIM, h);
        // ff = relu(h @ W1 + b1)   (W1 natural [C,FF] KN)
        tgemm<0,1><<<dim3(FF_DIM / 128, M_ROWS / 128), 256, GSM_KN>>>(
            h, W1 + (size_t)l * C_DIM * FF_DIM, ff, b1 + l * FF_DIM, nullptr, FF_DIM, C_DIM, 1);
        // x = x + ff @ W2 + b2   (W2 natural [FF,C] KN)
        tgemm<0,1><<<dim3(C_DIM / 128, M_ROWS / 128), 256, GSM_KN>>>(
            ff, W2 + (size_t)l * FF_DIM * C_DIM, x, b2 + l * C_DIM, x, C_DIM, FF_DIM, 0);
    }

    // final LN + tied-embedding logits: (2048,32000) = h @ tok^T (tok [V,K], NK)
    k_ln<<<M_ROWS, 256>>>(x, lnf_s, lnf_b, h);
    tgemm<1,1><<<dim3(V_SZ / 128, M_ROWS / 128), 256, GSM_NK>>>(
        h, tok, out, nullptr, nullptr, V_SZ, C_DIM, 0);
}

// round 6
// speedup vs baseline: 1.4100x; 1.4100x over previous
#include <cuda_runtime.h>
#include <cuda_fp16.h>
#include <cstdint>
#include <math.h>

// ---------------- model constants ----------------
#define C_DIM   1024
#define H_NUM   16
#define D_HEAD  64
#define L_NUM   8
#define T_SEQ   1024
#define B_SZ    2
#define M_ROWS  (B_SZ * T_SEQ)      // 2048
#define FF_DIM  4096
#define V_SZ    32000

// ---------------- device scratch ----------------
__device__ __align__(256) float  g_x   [M_ROWS * C_DIM];        // residual (fp32)
__device__ __align__(256) float  g_qkv [M_ROWS * 3 * C_DIM];    // qkv (fp32, attention input)
__device__ __align__(256) __half g_hh  [M_ROWS * C_DIM];        // LN out / attn out (GEMM A)
__device__ __align__(256) __half g_ffh [M_ROWS * FF_DIM];       // relu FF out (GEMM A)
__device__ __align__(256) __half g_wph [3 * C_DIM * C_DIM];     // packed qkv W [3C, C]
__device__ __align__(256) __half g_wth [FF_DIM * C_DIM];        // per-layer W [N, K]
__device__ __align__(256) __half g_tokh[V_SZ * C_DIM];          // tok embedding [V, K]

// ============================================================
// helpers
// ============================================================
__device__ __forceinline__ uint32_t smem_u32(const void* p) {
    uint32_t a;
    asm("{ .reg .u64 t; cvta.to.shared.u64 t, %1; cvt.u32.u64 %0, t; }" : "=r"(a) : "l"(p));
    return a;
}
__device__ __forceinline__ void cpa16(uint32_t dst, const void* src) {
    asm volatile("cp.async.cg.shared.global [%0], [%1], 16;" :: "r"(dst), "l"(src));
}
__device__ __forceinline__ void ldsm4(uint32_t& r0, uint32_t& r1, uint32_t& r2, uint32_t& r3,
                                      uint32_t a) {
    asm volatile("ldmatrix.sync.aligned.m8n8.x4.shared.b16 {%0,%1,%2,%3}, [%4];"
        : "=r"(r0), "=r"(r1), "=r"(r2), "=r"(r3) : "r"(a));
}
__device__ __forceinline__ void mma_f16(float& c0, float& c1, float& c2, float& c3,
                                        uint32_t a0, uint32_t a1, uint32_t a2, uint32_t a3,
                                        uint32_t b0, uint32_t b1) {
    asm volatile("mma.sync.aligned.m16n8k16.row.col.f32.f16.f16.f32 "
        "{%0,%1,%2,%3}, {%4,%5,%6,%7}, {%8,%9}, {%0,%1,%2,%3};"
        : "+f"(c0), "+f"(c1), "+f"(c2), "+f"(c3)
        : "r"(a0), "r"(a1), "r"(a2), "r"(a3), "r"(b0), "r"(b1));
}

// ============================================================
// FP16 mma.sync GEMM: C[M,N] = A[M,K] @ B^T  (A [M,K] half, B [N,K] half)
// CTA tile 128x128, BK=32, 2-stage cp.async, 8 warps (2x4), warp tile 64x32.
// OUTH=0: fp32 out (+bias)(+res). OUTH=1: half out (+bias)(+relu).
// ============================================================
#define ROWH     40                              // 32 + 8 pad halves (80B pitch)
#define ATILE_H  (128 * ROWH)                    // halves per matrix tile
#define STAGE_HB (2 * ATILE_H * 2)               // bytes per stage (A + B) = 20480
#define GSMH     (2 * STAGE_HB)                  // 40960

template<int OUTH>
__global__ __launch_bounds__(256, 2)
void hgemm(const __half* __restrict__ A, const __half* __restrict__ B,
           void* __restrict__ Cout, const float* __restrict__ bias,
           const float* __restrict__ res, int N, int K, int relu)
{
    extern __shared__ __half smh[];
    uint32_t sbase = smem_u32(smh);
    int tid  = threadIdx.x;
    int wid  = tid >> 5;
    int lane = tid & 31;
    int wm   = wid >> 2;          // 0..1
    int wn   = wid & 3;           // 0..3
    int bm = blockIdx.y << 7;
    int bn = blockIdx.x << 7;

    const __half* Ag = A + (size_t)bm * K;
    const __half* Bg = B + (size_t)bn * K;
    int NC = K >> 5;

    float acc[4][4][4];
#pragma unroll
    for (int mf = 0; mf < 4; mf++)
#pragma unroll
        for (int nf = 0; nf < 4; nf++)
#pragma unroll
            for (int k = 0; k < 4; k++) acc[mf][nf][k] = 0.f;

    // loader: each thread copies 2x16B for A and 2x16B for B
    auto load_tile = [&](int ch, int stage) {
        int k0 = ch << 5;
        uint32_t so = sbase + (uint32_t)stage * STAGE_HB;
        uint32_t bo = so + (uint32_t)ATILE_H * 2u;
#pragma unroll
        for (int i = 0; i < 2; i++) {
            int id = tid + (i << 8);
            int r = id >> 2, c = (id & 3) << 3;        // c in halves (8 per 16B)
            cpa16(so + ((uint32_t)(r * ROWH + c) << 1), Ag + (size_t)r * K + k0 + c);
            cpa16(bo + ((uint32_t)(r * ROWH + c) << 1), Bg + (size_t)r * K + k0 + c);
        }
    };

    load_tile(0, 0);
    asm volatile("cp.async.commit_group;");

    // ldmatrix per-lane address components
    uint32_t rA = (uint32_t)(wm << 6) + (lane & 7) + (((lane >> 3) & 1) << 3);
    uint32_t kA = ((lane >> 4) & 1) << 3;
    uint32_t rB = (uint32_t)(wn << 5) + (lane & 7) + (((lane >> 4) & 1) << 3);
    uint32_t kB = ((lane >> 3) & 1) << 3;

    for (int ch = 0; ch < NC; ch++) {
        if (ch > 0) __syncthreads();
        if (ch + 1 < NC) load_tile(ch + 1, (ch + 1) & 1);
        asm volatile("cp.async.commit_group;");
        asm volatile("cp.async.wait_group 1;");
        __syncthreads();

        uint32_t sA = sbase + (uint32_t)(ch & 1) * STAGE_HB;
        uint32_t sB = sA + (uint32_t)ATILE_H * 2u;
#pragma unroll
        for (int ks = 0; ks < 2; ks++) {
            uint32_t af[4][4], bf[4][2];
            uint32_t kofs = (uint32_t)(ks << 4);
#pragma unroll
            for (int mf = 0; mf < 4; mf++) {
                uint32_t a = sA + (((rA + (uint32_t)(mf << 4)) * ROWH + kA + kofs) << 1);
                ldsm4(af[mf][0], af[mf][1], af[mf][2], af[mf][3], a);
            }
#pragma unroll
            for (int p = 0; p < 2; p++) {
                uint32_t a = sB + (((rB + (uint32_t)(p << 4)) * ROWH + kB + kofs) << 1);
                ldsm4(bf[2 * p][0], bf[2 * p][1], bf[2 * p + 1][0], bf[2 * p + 1][1], a);
            }
#pragma unroll
            for (int mf = 0; mf < 4; mf++)
#pragma unroll
                for (int nf = 0; nf < 4; nf++)
                    mma_f16(acc[mf][nf][0], acc[mf][nf][1], acc[mf][nf][2], acc[mf][nf][3],
                            af[mf][0], af[mf][1], af[mf][2], af[mf][3],
                            bf[nf][0], bf[nf][1]);
        }
    }

    // ---- epilogue ----
    int row0 = bm + (wm << 6) + (lane >> 2);
    int col0 = bn + (wn << 5) + ((lane & 3) << 1);
#pragma unroll
    for (int mf = 0; mf < 4; mf++) {
#pragma unroll
        for (int half_ = 0; half_ < 2; half_++) {
            int row = row0 + (mf << 4) + half_ * 8;
#pragma unroll
            for (int nf = 0; nf < 4; nf++) {
                float vx = acc[mf][nf][half_ * 2 + 0];
                float vy = acc[mf][nf][half_ * 2 + 1];
                int c = (nf << 3);
                if (bias) {
                    vx += bias[col0 + c];
                    vy += bias[col0 + c + 1];
                }
                if (OUTH) {
                    if (relu) { vx = fmaxf(vx, 0.f); vy = fmaxf(vy, 0.f); }
                    __half2 hv = __floats2half2_rn(vx, vy);
                    *(__half2*)((__half*)Cout + (size_t)row * N + col0 + c) = hv;
                } else {
                    if (res) {
                        const float* rp = res + (size_t)row * N + col0 + c;
                        float2 r2 = *(const float2*)rp;
                        vx += r2.x; vy += r2.y;
                    }
                    float2 v; v.x = vx; v.y = vy;
                    *(float2*)((float*)Cout + (size_t)row * N + col0 + c) = v;
                }
            }
        }
    }
}

// ---------------- embedding ----------------
__global__ void k_embed(const int* __restrict__ idx,
                        const float* __restrict__ tok,
                        const float* __restrict__ pos,
                        float* __restrict__ x)
{
    int m = blockIdx.x;
    int c = threadIdx.x * 4;
    int t = m & (T_SEQ - 1);
    int v = idx[m];
    float4 a = *(const float4*)(tok + (size_t)v * C_DIM + c);
    float4 p = *(const float4*)(pos + (size_t)t * C_DIM + c);
    a.x += p.x; a.y += p.y; a.z += p.z; a.w += p.w;
    *(float4*)(x + (size_t)m * C_DIM + c) = a;
}

// ---------------- layernorm: fp32 in -> fp16 out (GEMM A operand) ----------------
__global__ void k_ln(const float* __restrict__ x,
                     const float* __restrict__ sc,
                     const float* __restrict__ bi,
                     __half* __restrict__ out)
{
    int m = blockIdx.x;
    int tid = threadIdx.x;                 // 256 threads
    int c = tid * 4;
    float4 v = *(const float4*)(x + (size_t)m * C_DIM + c);
    float s = v.x + v.y + v.z + v.w;
    float q = v.x*v.x + v.y*v.y + v.z*v.z + v.w*v.w;

    __shared__ float rs[8], rq[8];
#pragma unroll
    for (int o = 16; o > 0; o >>= 1) {
        s += __shfl_xor_sync(0xffffffffu, s, o);
        q += __shfl_xor_sync(0xffffffffu, q, o);
    }
    if ((tid & 31) == 0) { rs[tid >> 5] = s; rq[tid >> 5] = q; }
    __syncthreads();
    float sum = 0.f, sq = 0.f;
#pragma unroll
    for (int w = 0; w < 8; w++) { sum += rs[w]; sq += rq[w]; }

    float mu = sum * (1.0f / C_DIM);
    float var = sq * (1.0f / C_DIM) - mu * mu;
    float rstd = rsqrtf(var + 1e-5f);

    float4 svv = *(const float4*)(sc + c);
    float4 bvv = *(const float4*)(bi + c);
    __half2 p0 = __floats2half2_rn((v.x - mu) * rstd * svv.x + bvv.x,
                                   (v.y - mu) * rstd * svv.y + bvv.y);
    __half2 p1 = __floats2half2_rn((v.z - mu) * rstd * svv.z + bvv.z,
                                   (v.w - mu) * rstd * svv.w + bvv.w);
    uint2 st;
    st.x = *(uint32_t*)&p0;
    st.y = *(uint32_t*)&p1;
    *(uint2*)(out + (size_t)m * C_DIM + c) = st;
}

// ---------------- pack qkv weights (L,H,C,D) -> [3C, C] half (N,K layout) ----------------
__global__ __launch_bounds__(256)
void k_packQKV(const float* __restrict__ Wq, const float* __restrict__ Wk,
               const float* __restrict__ Wv, __half* __restrict__ out, int l)
{
    __shared__ float t[32][65];
    int b  = blockIdx.x;
    int kb = b & 31;            // k0 / 32
    int hh = (b >> 5) & 15;
    int s  = b >> 9;
    const float* W = (s == 0) ? Wq : ((s == 1) ? Wk : Wv);
    const float* Wb = W + ((size_t)l * H_NUM + hh) * C_DIM * D_HEAD + (size_t)(kb << 5) * D_HEAD;
    int tid = threadIdx.x;
#pragma unroll
    for (int i = 0; i < 8; i++) {
        int idx = tid + (i << 8);
        int r = idx >> 6, d = idx & 63;
        t[r][d] = Wb[(size_t)r * D_HEAD + d];
    }
    __syncthreads();
    int n0 = s * 1024 + hh * 64;
#pragma unroll
    for (int i = 0; i < 8; i++) {
        int idx = tid + (i << 8);
        int d = idx >> 5, kk = idx & 31;
        out[(size_t)(n0 + d) * C_DIM + (kb << 5) + kk] = __float2half_rn(t[kk][d]);
    }
}

// ---------------- weight transpose-convert [K,N] fp32 -> [N,K] half ----------------
__global__ __launch_bounds__(256)
void k_wcvt(const float* __restrict__ in, __half* __restrict__ out, int K, int N)
{
    __shared__ float t[32][33];
    int n0 = blockIdx.x << 5;
    int k0 = blockIdx.y << 5;
    int c = threadIdx.x & 31, r = threadIdx.x >> 5;
#pragma unroll
    for (int i = 0; i < 4; i++)
        t[r + i * 8][c] = in[(size_t)(k0 + r + i * 8) * N + n0 + c];
    __syncthreads();
#pragma unroll
    for (int i = 0; i < 4; i++)
        out[(size_t)(n0 + r + i * 8) * K + k0 + c] = __float2half_rn(t[c][r + i * 8]);
}

// ---------------- tok embedding convert fp32 -> half ([V,K] both) ----------------
__global__ __launch_bounds__(256)
void k_tokcvt(const float* __restrict__ in, __half* __restrict__ out)
{
    size_t i = ((size_t)blockIdx.x * 256 + threadIdx.x) * 8;
    float4 a = *(const float4*)(in + i);
    float4 b = *(const float4*)(in + i + 4);
    __half2 h0 = __floats2half2_rn(a.x, a.y);
    __half2 h1 = __floats2half2_rn(a.z, a.w);
    __half2 h2 = __floats2half2_rn(b.x, b.y);
    __half2 h3 = __floats2half2_rn(b.z, b.w);
    uint4 st;
    st.x = *(uint32_t*)&h0; st.y = *(uint32_t*)&h1;
    st.z = *(uint32_t*)&h2; st.w = *(uint32_t*)&h3;
    *(uint4*)(out + i) = st;
}

// ---------------- causal flash attention: fp32 qkv in, half out ----------------
__global__ __launch_bounds__(256)
void k_attn(const float* __restrict__ qkv, __half* __restrict__ outb)
{
    __shared__ float qs[64][64];
    __shared__ float ks[32][65];
    __shared__ float vs[32][65];
    __shared__ float ps[64][33];

    int qt  = blockIdx.x;
    int b   = blockIdx.y >> 4;
    int hh  = blockIdx.y & 15;
    int tid = threadIdx.x;
    int tx  = tid & 15, ty = tid >> 4;

    const float* qbase = qkv + (size_t)(b * T_SEQ + qt * 64) * 3072 + hh * 64;
#pragma unroll
    for (int e = 0; e < 16; e++) {
        int i = tid + e * 256;
        int r = i >> 6, d = i & 63;
        qs[r][d] = qbase[(size_t)r * 3072 + d] * 0.125f;
    }

    float m_r[4], l_r[4], oa[4][4];
#pragma unroll
    for (int i = 0; i < 4; i++) {
        m_r[i] = -1e30f; l_r[i] = 0.f;
#pragma unroll
        for (int j = 0; j < 4; j++) oa[i][j] = 0.f;
    }

    const float* kb = qkv + (size_t)(b * T_SEQ) * 3072 + 1024 + hh * 64;
    const float* vb = qkv + (size_t)(b * T_SEQ) * 3072 + 2048 + hh * 64;

    int nkt = 2 * qt + 2;
    for (int kt = 0; kt < nkt; kt++) {
        __syncthreads();
#pragma unroll
        for (int e = 0; e < 8; e++) {
            int i = tid + e * 256;
            int r = i >> 6, d = i & 63;
            ks[r][d] = kb[(size_t)(kt * 32 + r) * 3072 + d];
            vs[r][d] = vb[(size_t)(kt * 32 + r) * 3072 + d];
        }
        __syncthreads();

        float sv[4][2];
#pragma unroll
        for (int i = 0; i < 4; i++) { sv[i][0] = 0.f; sv[i][1] = 0.f; }
#pragma unroll 8
        for (int d = 0; d < 64; d++) {
            float b0 = ks[2 * tx + 0][d];
            float b1 = ks[2 * tx + 1][d];
#pragma unroll
            for (int i = 0; i < 4; i++) {
                float a = qs[4 * ty + i][d];
                sv[i][0] += a * b0;
                sv[i][1] += a * b1;
            }
        }

        if (kt >= 2 * qt) {
#pragma unroll
            for (int i = 0; i < 4; i++)
#pragma unroll
                for (int j = 0; j < 2; j++) {
                    int sg = kt * 32 + 2 * tx + j;
                    int tg = qt * 64 + 4 * ty + i;
                    if (sg > tg) sv[i][j] = -1e30f;
                }
        }

#pragma unroll
        for (int i = 0; i < 4; i++) {
            float mloc = fmaxf(sv[i][0], sv[i][1]);
#pragma unroll
            for (int o = 8; o > 0; o >>= 1)
                mloc = fmaxf(mloc, __shfl_xor_sync(0xffffffffu, mloc, o));
            float mnew = fmaxf(m_r[i], mloc);
            float p0 = expf(sv[i][0] - mnew);
            float p1 = expf(sv[i][1] - mnew);
            float corr = expf(m_r[i] - mnew);
            float rsum = p0 + p1;
#pragma unroll
            for (int o = 8; o > 0; o >>= 1)
                rsum += __shfl_xor_sync(0xffffffffu, rsum, o);
            l_r[i] = l_r[i] * corr + rsum;
            m_r[i] = mnew;
            oa[i][0] *= corr; oa[i][1] *= corr; oa[i][2] *= corr; oa[i][3] *= corr;
            ps[4 * ty + i][2 * tx + 0] = p0;
            ps[4 * ty + i][2 * tx + 1] = p1;
        }
        __syncthreads();

#pragma unroll 4
        for (int s = 0; s < 32; s++) {
            float b0 = vs[s][4 * tx + 0];
            float b1 = vs[s][4 * tx + 1];
            float b2 = vs[s][4 * tx + 2];
            float b3 = vs[s][4 * tx + 3];
#pragma unroll
            for (int i = 0; i < 4; i++) {
                float a = ps[4 * ty + i][s];
                oa[i][0] += a * b0;
                oa[i][1] += a * b1;
                oa[i][2] += a * b2;
                oa[i][3] += a * b3;
            }
        }
    }

    __half* ob = outb + (size_t)(b * T_SEQ + qt * 64) * C_DIM + hh * 64;
#pragma unroll
    for (int i = 0; i < 4; i++) {
        float inv = 1.0f / l_r[i];
        __half2 h0 = __floats2half2_rn(oa[i][0] * inv, oa[i][1] * inv);
        __half2 h1 = __floats2half2_rn(oa[i][2] * inv, oa[i][3] * inv);
        uint2 st;
        st.x = *(uint32_t*)&h0;
        st.y = *(uint32_t*)&h1;
        *(uint2*)(ob + (size_t)(4 * ty + i) * C_DIM + 4 * tx) = st;
    }
}

// ---------------- launcher ----------------
extern "C" void kernel_launch(void* const* d_in, const int* in_sizes, int n_in,
                              void* d_out, int out_size)
{
    const int*   idx    = (const int*)  d_in[0];
    const float* tok    = (const float*)d_in[1];
    const float* pos    = (const float*)d_in[2];
    const float* ln1_s  = (const float*)d_in[3];
    const float* ln1_b  = (const float*)d_in[4];
    const float* Wq     = (const float*)d_in[5];
    const float* Wk     = (const float*)d_in[6];
    const float* Wv     = (const float*)d_in[7];
    const float* Wo     = (const float*)d_in[8];
    const float* bo     = (const float*)d_in[9];
    const float* ln2_s  = (const float*)d_in[10];
    const float* ln2_b  = (const float*)d_in[11];
    const float* W1     = (const float*)d_in[12];
    const float* b1     = (const float*)d_in[13];
    const float* W2     = (const float*)d_in[14];
    const float* b2     = (const float*)d_in[15];
    const float* lnf_s  = (const float*)d_in[16];
    const float* lnf_b  = (const float*)d_in[17];
    float* out = (float*)d_out;

    float *x, *qkv;
    __half *hh, *ffh, *wph, *wth, *tokh;
    cudaGetSymbolAddress((void**)&x,    g_x);
    cudaGetSymbolAddress((void**)&qkv,  g_qkv);
    cudaGetSymbolAddress((void**)&hh,   g_hh);
    cudaGetSymbolAddress((void**)&ffh,  g_ffh);
    cudaGetSymbolAddress((void**)&wph,  g_wph);
    cudaGetSymbolAddress((void**)&wth,  g_wth);
    cudaGetSymbolAddress((void**)&tokh, g_tokh);

    cudaFuncSetAttribute(hgemm<0>, cudaFuncAttributeMaxDynamicSharedMemorySize, GSMH);
    cudaFuncSetAttribute(hgemm<1>, cudaFuncAttributeMaxDynamicSharedMemorySize, GSMH);

    // one-time per launch: tok embedding -> half
    k_tokcvt<<<(V_SZ * C_DIM) / (256 * 8), 256>>>(tok, tokh);
    k_embed<<<M_ROWS, 256>>>(idx, tok, pos, x);

    for (int l = 0; l < L_NUM; l++) {
        // LN1 -> half
        k_ln<<<M_ROWS, 256>>>(x, ln1_s + l * C_DIM, ln1_b + l * C_DIM, hh);
        // pack qkv weights [3C, C] half
        k_packQKV<<<3 * 16 * 32, 256>>>(Wq, Wk, Wv, wph, l);
        // qkv = hh @ wph^T  -> fp32
        hgemm<0><<<dim3(3072 / 128, M_ROWS / 128), 256, GSMH>>>(
            hh, wph, qkv, nullptr, nullptr, 3072, C_DIM, 0);
        // attention -> hh (half)
        k_attn<<<dim3(T_SEQ / 64, B_SZ * H_NUM), 256>>>(qkv, hh);
        // x = x + hh @ Wo^T + bo
        k_wcvt<<<dim3(C_DIM / 32, C_DIM / 32), 256>>>(
            Wo + (size_t)l * C_DIM * C_DIM, wth, C_DIM, C_DIM);
        hgemm<0><<<dim3(C_DIM / 128, M_ROWS / 128), 256, GSMH>>>(
            hh, wth, x, bo + l * C_DIM, x, C_DIM, C_DIM, 0);
        // LN2 -> half
        k_ln<<<M_ROWS, 256>>>(x, ln2_s + l * C_DIM, ln2_b + l * C_DIM, hh);
        // ffh = relu(hh @ W1^T + b1) -> half
        k_wcvt<<<dim3(FF_DIM / 32, C_DIM / 32), 256>>>(
            W1 + (size_t)l * C_DIM * FF_DIM, wth, C_DIM, FF_DIM);
        hgemm<1><<<dim3(FF_DIM / 128, M_ROWS / 128), 256, GSMH>>>(
            hh, wth, ffh, b1 + l * FF_DIM, nullptr, FF_DIM, C_DIM, 1);
        // x = x + ffh @ W2^T + b2
        k_wcvt<<<dim3(C_DIM / 32, FF_DIM / 32), 256>>>(
            W2 + (size_t)l * FF_DIM * C_DIM, wth, FF_DIM, C_DIM);
        hgemm<0><<<dim3(C_DIM / 128, M_ROWS / 128), 256, GSMH>>>(
            ffh, wth, x, b2 + l * C_DIM, x, C_DIM, FF_DIM, 0);
    }

    // final LN + tied-embedding logits
    k_ln<<<M_ROWS, 256>>>(x, lnf_s, lnf_b, hh);
    hgemm<0><<<dim3(V_SZ / 128, M_ROWS / 128), 256, GSMH>>>(
        hh, tokh, out, nullptr, nullptr, V_SZ, C_DIM, 0);
}

// round 7
// speedup vs baseline: 2.1694x; 1.5385x over previous
#include <cuda_runtime.h>
#include <cuda_fp16.h>
#include <cstdint>
#include <math.h>

// ---------------- model constants ----------------
#define C_DIM   1024
#define H_NUM   16
#define D_HEAD  64
#define L_NUM   8
#define T_SEQ   1024
#define B_SZ    2
#define M_ROWS  (B_SZ * T_SEQ)      // 2048
#define FF_DIM  4096
#define V_SZ    32000

// ---------------- device scratch ----------------
__device__ __align__(256) float  g_x   [M_ROWS * C_DIM];        // residual (fp32)
__device__ __align__(256) __half g_qkvh[M_ROWS * 3 * C_DIM];    // qkv (half)
__device__ __align__(256) __half g_hh  [M_ROWS * C_DIM];        // LN out / attn out (GEMM A)
__device__ __align__(256) __half g_ffh [M_ROWS * FF_DIM];       // relu FF out (GEMM A)
__device__ __align__(256) __half g_wph [3 * C_DIM * C_DIM];     // packed qkv W [3C, C]
__device__ __align__(256) __half g_wth [FF_DIM * C_DIM];        // per-layer W [N, K]
__device__ __align__(256) __half g_tokh[V_SZ * C_DIM];          // tok embedding [V, K]

// ============================================================
// helpers
// ============================================================
__device__ __forceinline__ uint32_t smem_u32(const void* p) {
    uint32_t a;
    asm("{ .reg .u64 t; cvta.to.shared.u64 t, %1; cvt.u32.u64 %0, t; }" : "=r"(a) : "l"(p));
    return a;
}
__device__ __forceinline__ void cpa16(uint32_t dst, const void* src) {
    asm volatile("cp.async.cg.shared.global [%0], [%1], 16;" :: "r"(dst), "l"(src));
}
__device__ __forceinline__ void ldsm4(uint32_t& r0, uint32_t& r1, uint32_t& r2, uint32_t& r3,
                                      uint32_t a) {
    asm volatile("ldmatrix.sync.aligned.m8n8.x4.shared.b16 {%0,%1,%2,%3}, [%4];"
        : "=r"(r0), "=r"(r1), "=r"(r2), "=r"(r3) : "r"(a));
}
__device__ __forceinline__ void ldsm4t(uint32_t& r0, uint32_t& r1, uint32_t& r2, uint32_t& r3,
                                       uint32_t a) {
    asm volatile("ldmatrix.sync.aligned.m8n8.x4.trans.shared.b16 {%0,%1,%2,%3}, [%4];"
        : "=r"(r0), "=r"(r1), "=r"(r2), "=r"(r3) : "r"(a));
}
__device__ __forceinline__ void mma_f16(float& c0, float& c1, float& c2, float& c3,
                                        uint32_t a0, uint32_t a1, uint32_t a2, uint32_t a3,
                                        uint32_t b0, uint32_t b1) {
    asm volatile("mma.sync.aligned.m16n8k16.row.col.f32.f16.f16.f32 "
        "{%0,%1,%2,%3}, {%4,%5,%6,%7}, {%8,%9}, {%0,%1,%2,%3};"
        : "+f"(c0), "+f"(c1), "+f"(c2), "+f"(c3)
        : "r"(a0), "r"(a1), "r"(a2), "r"(a3), "r"(b0), "r"(b1));
}

// ============================================================
// FP16 mma.sync GEMM: C[M,N] = A[M,K] @ B^T  (A [M,K] half, B [N,K] half)
// CTA tile 128x128, BK=32, 2-stage cp.async, 8 warps (2x4), warp tile 64x32.
// OUTH=0: fp32 out (+bias)(+res). OUTH=1: half out (+bias)(+relu).
// ============================================================
#define ROWH     40                              // 32 + 8 pad halves (80B pitch)
#define ATILE_H  (128 * ROWH)                    // halves per matrix tile
#define STAGE_HB (2 * ATILE_H * 2)               // bytes per stage (A + B) = 20480
#define GSMH     (2 * STAGE_HB)                  // 40960

template<int OUTH>
__global__ __launch_bounds__(256, 2)
void hgemm(const __half* __restrict__ A, const __half* __restrict__ B,
           void* __restrict__ Cout, const float* __restrict__ bias,
           const float* __restrict__ res, int N, int K, int relu)
{
    extern __shared__ __half smh[];
    uint32_t sbase = smem_u32(smh);
    int tid  = threadIdx.x;
    int wid  = tid >> 5;
    int lane = tid & 31;
    int wm   = wid >> 2;          // 0..1
    int wn   = wid & 3;           // 0..3
    int bm = blockIdx.y << 7;
    int bn = blockIdx.x << 7;

    const __half* Ag = A + (size_t)bm * K;
    const __half* Bg = B + (size_t)bn * K;
    int NC = K >> 5;

    float acc[4][4][4];
#pragma unroll
    for (int mf = 0; mf < 4; mf++)
#pragma unroll
        for (int nf = 0; nf < 4; nf++)
#pragma unroll
            for (int k = 0; k < 4; k++) acc[mf][nf][k] = 0.f;

    auto load_tile = [&](int ch, int stage) {
        int k0 = ch << 5;
        uint32_t so = sbase + (uint32_t)stage * STAGE_HB;
        uint32_t bo = so + (uint32_t)ATILE_H * 2u;
#pragma unroll
        for (int i = 0; i < 2; i++) {
            int id = tid + (i << 8);
            int r = id >> 2, c = (id & 3) << 3;
            cpa16(so + ((uint32_t)(r * ROWH + c) << 1), Ag + (size_t)r * K + k0 + c);
            cpa16(bo + ((uint32_t)(r * ROWH + c) << 1), Bg + (size_t)r * K + k0 + c);
        }
    };

    load_tile(0, 0);
    asm volatile("cp.async.commit_group;");

    uint32_t rA = (uint32_t)(wm << 6) + (lane & 7) + (((lane >> 3) & 1) << 3);
    uint32_t kA = ((lane >> 4) & 1) << 3;
    uint32_t rB = (uint32_t)(wn << 5) + (lane & 7) + (((lane >> 4) & 1) << 3);
    uint32_t kB = ((lane >> 3) & 1) << 3;

    for (int ch = 0; ch < NC; ch++) {
        if (ch > 0) __syncthreads();
        if (ch + 1 < NC) load_tile(ch + 1, (ch + 1) & 1);
        asm volatile("cp.async.commit_group;");
        asm volatile("cp.async.wait_group 1;");
        __syncthreads();

        uint32_t sA = sbase + (uint32_t)(ch & 1) * STAGE_HB;
        uint32_t sB = sA + (uint32_t)ATILE_H * 2u;
#pragma unroll
        for (int ks = 0; ks < 2; ks++) {
            uint32_t af[4][4], bf[4][2];
            uint32_t kofs = (uint32_t)(ks << 4);
#pragma unroll
            for (int mf = 0; mf < 4; mf++) {
                uint32_t a = sA + (((rA + (uint32_t)(mf << 4)) * ROWH + kA + kofs) << 1);
                ldsm4(af[mf][0], af[mf][1], af[mf][2], af[mf][3], a);
            }
#pragma unroll
            for (int p = 0; p < 2; p++) {
                uint32_t a = sB + (((rB + (uint32_t)(p << 4)) * ROWH + kB + kofs) << 1);
                ldsm4(bf[2 * p][0], bf[2 * p][1], bf[2 * p + 1][0], bf[2 * p + 1][1], a);
            }
#pragma unroll
            for (int mf = 0; mf < 4; mf++)
#pragma unroll
                for (int nf = 0; nf < 4; nf++)
                    mma_f16(acc[mf][nf][0], acc[mf][nf][1], acc[mf][nf][2], acc[mf][nf][3],
                            af[mf][0], af[mf][1], af[mf][2], af[mf][3],
                            bf[nf][0], bf[nf][1]);
        }
    }

    // ---- epilogue ----
    int row0 = bm + (wm << 6) + (lane >> 2);
    int col0 = bn + (wn << 5) + ((lane & 3) << 1);
#pragma unroll
    for (int mf = 0; mf < 4; mf++) {
#pragma unroll
        for (int half_ = 0; half_ < 2; half_++) {
            int row = row0 + (mf << 4) + half_ * 8;
#pragma unroll
            for (int nf = 0; nf < 4; nf++) {
                float vx = acc[mf][nf][half_ * 2 + 0];
                float vy = acc[mf][nf][half_ * 2 + 1];
                int c = (nf << 3);
                if (bias) {
                    vx += bias[col0 + c];
                    vy += bias[col0 + c + 1];
                }
                if (OUTH) {
                    if (relu) { vx = fmaxf(vx, 0.f); vy = fmaxf(vy, 0.f); }
                    __half2 hv = __floats2half2_rn(vx, vy);
                    *(__half2*)((__half*)Cout + (size_t)row * N + col0 + c) = hv;
                } else {
                    if (res) {
                        const float* rp = res + (size_t)row * N + col0 + c;
                        float2 r2 = *(const float2*)rp;
                        vx += r2.x; vy += r2.y;
                    }
                    float2 v; v.x = vx; v.y = vy;
                    *(float2*)((float*)Cout + (size_t)row * N + col0 + c) = v;
                }
            }
        }
    }
}

// ---------------- embedding ----------------
__global__ void k_embed(const int* __restrict__ idx,
                        const float* __restrict__ tok,
                        const float* __restrict__ pos,
                        float* __restrict__ x)
{
    int m = blockIdx.x;
    int c = threadIdx.x * 4;
    int t = m & (T_SEQ - 1);
    int v = idx[m];
    float4 a = *(const float4*)(tok + (size_t)v * C_DIM + c);
    float4 p = *(const float4*)(pos + (size_t)t * C_DIM + c);
    a.x += p.x; a.y += p.y; a.z += p.z; a.w += p.w;
    *(float4*)(x + (size_t)m * C_DIM + c) = a;
}

// ---------------- layernorm: fp32 in -> fp16 out ----------------
__global__ void k_ln(const float* __restrict__ x,
                     const float* __restrict__ sc,
                     const float* __restrict__ bi,
                     __half* __restrict__ out)
{
    int m = blockIdx.x;
    int tid = threadIdx.x;                 // 256 threads
    int c = tid * 4;
    float4 v = *(const float4*)(x + (size_t)m * C_DIM + c);
    float s = v.x + v.y + v.z + v.w;
    float q = v.x*v.x + v.y*v.y + v.z*v.z + v.w*v.w;

    __shared__ float rs[8], rq[8];
#pragma unroll
    for (int o = 16; o > 0; o >>= 1) {
        s += __shfl_xor_sync(0xffffffffu, s, o);
        q += __shfl_xor_sync(0xffffffffu, q, o);
    }
    if ((tid & 31) == 0) { rs[tid >> 5] = s; rq[tid >> 5] = q; }
    __syncthreads();
    float sum = 0.f, sq = 0.f;
#pragma unroll
    for (int w = 0; w < 8; w++) { sum += rs[w]; sq += rq[w]; }

    float mu = sum * (1.0f / C_DIM);
    float var = sq * (1.0f / C_DIM) - mu * mu;
    float rstd = rsqrtf(var + 1e-5f);

    float4 svv = *(const float4*)(sc + c);
    float4 bvv = *(const float4*)(bi + c);
    __half2 p0 = __floats2half2_rn((v.x - mu) * rstd * svv.x + bvv.x,
                                   (v.y - mu) * rstd * svv.y + bvv.y);
    __half2 p1 = __floats2half2_rn((v.z - mu) * rstd * svv.z + bvv.z,
                                   (v.w - mu) * rstd * svv.w + bvv.w);
    uint2 st;
    st.x = *(uint32_t*)&p0;
    st.y = *(uint32_t*)&p1;
    *(uint2*)(out + (size_t)m * C_DIM + c) = st;
}

// ---------------- pack qkv weights (L,H,C,D) -> [3C, C] half ----------------
__global__ __launch_bounds__(256)
void k_packQKV(const float* __restrict__ Wq, const float* __restrict__ Wk,
               const float* __restrict__ Wv, __half* __restrict__ out, int l)
{
    __shared__ float t[32][65];
    int b  = blockIdx.x;
    int kb = b & 31;
    int hh = (b >> 5) & 15;
    int s  = b >> 9;
    const float* W = (s == 0) ? Wq : ((s == 1) ? Wk : Wv);
    const float* Wb = W + ((size_t)l * H_NUM + hh) * C_DIM * D_HEAD + (size_t)(kb << 5) * D_HEAD;
    int tid = threadIdx.x;
#pragma unroll
    for (int i = 0; i < 8; i++) {
        int idx = tid + (i << 8);
        int r = idx >> 6, d = idx & 63;
        t[r][d] = Wb[(size_t)r * D_HEAD + d];
    }
    __syncthreads();
    int n0 = s * 1024 + hh * 64;
#pragma unroll
    for (int i = 0; i < 8; i++) {
        int idx = tid + (i << 8);
        int d = idx >> 5, kk = idx & 31;
        out[(size_t)(n0 + d) * C_DIM + (kb << 5) + kk] = __float2half_rn(t[kk][d]);
    }
}

// ---------------- weight transpose-convert [K,N] fp32 -> [N,K] half ----------------
__global__ __launch_bounds__(256)
void k_wcvt(const float* __restrict__ in, __half* __restrict__ out, int K, int N)
{
    __shared__ float t[32][33];
    int n0 = blockIdx.x << 5;
    int k0 = blockIdx.y << 5;
    int c = threadIdx.x & 31, r = threadIdx.x >> 5;
#pragma unroll
    for (int i = 0; i < 4; i++)
        t[r + i * 8][c] = in[(size_t)(k0 + r + i * 8) * N + n0 + c];
    __syncthreads();
#pragma unroll
    for (int i = 0; i < 4; i++)
        out[(size_t)(n0 + r + i * 8) * K + k0 + c] = __float2half_rn(t[c][r + i * 8]);
}

// ---------------- tok embedding convert fp32 -> half ----------------
__global__ __launch_bounds__(256)
void k_tokcvt(const float* __restrict__ in, __half* __restrict__ out)
{
    size_t i = ((size_t)blockIdx.x * 256 + threadIdx.x) * 8;
    float4 a = *(const float4*)(in + i);
    float4 b = *(const float4*)(in + i + 4);
    __half2 h0 = __floats2half2_rn(a.x, a.y);
    __half2 h1 = __floats2half2_rn(a.z, a.w);
    __half2 h2 = __floats2half2_rn(b.x, b.y);
    __half2 h3 = __floats2half2_rn(b.z, b.w);
    uint4 st;
    st.x = *(uint32_t*)&h0; st.y = *(uint32_t*)&h1;
    st.z = *(uint32_t*)&h2; st.w = *(uint32_t*)&h3;
    *(uint4*)(out + i) = st;
}

// ============================================================
// Tensor-core causal flash attention.
// grid (16, 32): 64-query tile per block, (b,h) per blockIdx.y.
// 128 threads = 4 warps; warp w owns query rows 16w..16w+15.
// K/V 64-key tiles, double-buffered cp.async.
// ============================================================
#define AT_PAD  72
#define AT_TILEB (64 * AT_PAD * 2)

__global__ __launch_bounds__(128)
void k_attn(const __half* __restrict__ qkvh, __half* __restrict__ outb)
{
    __shared__ __half Qs[64][AT_PAD];
    __shared__ __half Ks[2][64][AT_PAD];
    __shared__ __half Vs[2][64][AT_PAD];

    int qt = blockIdx.x;
    int b  = blockIdx.y >> 4;
    int hh = blockIdx.y & 15;
    int tid = threadIdx.x;
    int wid = tid >> 5, lane = tid & 31;

    const __half* qp = qkvh + ((size_t)(b * T_SEQ + qt * 64)) * 3072 + hh * 64;
    const __half* kp = qkvh + ((size_t)(b * T_SEQ)) * 3072 + 1024 + hh * 64;
    const __half* vp = kp + 1024;

    uint32_t sQ = smem_u32(Qs);
    uint32_t sK = smem_u32(Ks);
    uint32_t sV = smem_u32(Vs);

    // prologue: Q + K0 + V0
#pragma unroll
    for (int i = 0; i < 4; i++) {
        int id = tid + (i << 7);
        int r = id >> 3, c = (id & 7) << 3;
        uint32_t off = (uint32_t)(r * AT_PAD + c) << 1;
        cpa16(sQ + off, qp + (size_t)r * 3072 + c);
        cpa16(sK + off, kp + (size_t)r * 3072 + c);
        cpa16(sV + off, vp + (size_t)r * 3072 + c);
    }
    asm volatile("cp.async.commit_group;");

    uint32_t qf[4][4];
    float oa[8][4];
    float m0 = -1e30f, m1 = -1e30f, l0 = 0.f, l1 = 0.f;
#pragma unroll
    for (int i = 0; i < 8; i++) { oa[i][0] = oa[i][1] = oa[i][2] = oa[i][3] = 0.f; }

    for (int kt = 0; kt <= qt; kt++) {
        if (kt > 0) __syncthreads();
        if (kt < qt) {
            uint32_t st = (uint32_t)((kt + 1) & 1) * AT_TILEB;
#pragma unroll
            for (int i = 0; i < 4; i++) {
                int id = tid + (i << 7);
                int r = id >> 3, c = (id & 7) << 3;
                uint32_t off = (uint32_t)(r * AT_PAD + c) << 1;
                cpa16(sK + st + off, kp + (size_t)((kt + 1) * 64 + r) * 3072 + c);
                cpa16(sV + st + off, vp + (size_t)((kt + 1) * 64 + r) * 3072 + c);
            }
        }
        asm volatile("cp.async.commit_group;");
        asm volatile("cp.async.wait_group 1;");
        __syncthreads();

        if (kt == 0) {   // load Q fragments once
            uint32_t rAq = (uint32_t)(wid << 4) + (lane & 7) + (((lane >> 3) & 1) << 3);
#pragma unroll
            for (int kc = 0; kc < 4; kc++) {
                uint32_t kAq = (((lane >> 4) & 1) << 3) + (kc << 4);
                ldsm4(qf[kc][0], qf[kc][1], qf[kc][2], qf[kc][3],
                      sQ + ((rAq * AT_PAD + kAq) << 1));
            }
        }

        uint32_t sKt = sK + (uint32_t)(kt & 1) * AT_TILEB;
        uint32_t sVt = sV + (uint32_t)(kt & 1) * AT_TILEB;

        // ---- S = Q @ K^T ----
        float s[8][4];
#pragma unroll
        for (int i = 0; i < 8; i++) { s[i][0] = s[i][1] = s[i][2] = s[i][3] = 0.f; }
        uint32_t rBk = (lane & 7) + (((lane >> 4) & 1) << 3);
        uint32_t kBo = ((lane >> 3) & 1) << 3;
#pragma unroll
        for (int kc = 0; kc < 4; kc++) {
#pragma unroll
            for (int p = 0; p < 4; p++) {
                uint32_t b0, b1, b2, b3;
                ldsm4(b0, b1, b2, b3,
                      sKt + (((rBk + (uint32_t)(p << 4)) * AT_PAD + kBo + (kc << 4)) << 1));
                mma_f16(s[2*p][0], s[2*p][1], s[2*p][2], s[2*p][3],
                        qf[kc][0], qf[kc][1], qf[kc][2], qf[kc][3], b0, b1);
                mma_f16(s[2*p+1][0], s[2*p+1][1], s[2*p+1][2], s[2*p+1][3],
                        qf[kc][0], qf[kc][1], qf[kc][2], qf[kc][3], b2, b3);
            }
        }
#pragma unroll
        for (int i = 0; i < 8; i++) {
            s[i][0] *= 0.125f; s[i][1] *= 0.125f; s[i][2] *= 0.125f; s[i][3] *= 0.125f;
        }
        if (kt == qt) {   // causal mask on diagonal tile
            int r0 = (wid << 4) + (lane >> 2);
#pragma unroll
            for (int nf = 0; nf < 8; nf++) {
                int c0 = (nf << 3) + ((lane & 3) << 1);
                if (c0     > r0)     s[nf][0] = -1e30f;
                if (c0 + 1 > r0)     s[nf][1] = -1e30f;
                if (c0     > r0 + 8) s[nf][2] = -1e30f;
                if (c0 + 1 > r0 + 8) s[nf][3] = -1e30f;
            }
        }

        // ---- online softmax ----
        float mx0 = s[0][0], mx1 = s[0][2];
#pragma unroll
        for (int nf = 0; nf < 8; nf++) {
            mx0 = fmaxf(mx0, fmaxf(s[nf][0], s[nf][1]));
            mx1 = fmaxf(mx1, fmaxf(s[nf][2], s[nf][3]));
        }
        mx0 = fmaxf(mx0, __shfl_xor_sync(0xffffffffu, mx0, 1));
        mx0 = fmaxf(mx0, __shfl_xor_sync(0xffffffffu, mx0, 2));
        mx1 = fmaxf(mx1, __shfl_xor_sync(0xffffffffu, mx1, 1));
        mx1 = fmaxf(mx1, __shfl_xor_sync(0xffffffffu, mx1, 2));
        float mn0 = fmaxf(m0, mx0), mn1 = fmaxf(m1, mx1);
        float cr0 = __expf(m0 - mn0), cr1 = __expf(m1 - mn1);
        float rs0 = 0.f, rs1 = 0.f;
        uint32_t pa[4][4];
#pragma unroll
        for (int nf = 0; nf < 8; nf++) {
            float p0 = __expf(s[nf][0] - mn0);
            float p1 = __expf(s[nf][1] - mn0);
            float p2 = __expf(s[nf][2] - mn1);
            float p3 = __expf(s[nf][3] - mn1);
            rs0 += p0 + p1; rs1 += p2 + p3;
            __half2 h01 = __floats2half2_rn(p0, p1);
            __half2 h23 = __floats2half2_rn(p2, p3);
            int kc = nf >> 1, hi = (nf & 1) << 1;
            pa[kc][hi]     = *(uint32_t*)&h01;
            pa[kc][hi + 1] = *(uint32_t*)&h23;
        }
        rs0 += __shfl_xor_sync(0xffffffffu, rs0, 1);
        rs0 += __shfl_xor_sync(0xffffffffu, rs0, 2);
        rs1 += __shfl_xor_sync(0xffffffffu, rs1, 1);
        rs1 += __shfl_xor_sync(0xffffffffu, rs1, 2);
        l0 = l0 * cr0 + rs0; l1 = l1 * cr1 + rs1;
        m0 = mn0; m1 = mn1;
#pragma unroll
        for (int i = 0; i < 8; i++) {
            oa[i][0] *= cr0; oa[i][1] *= cr0; oa[i][2] *= cr1; oa[i][3] *= cr1;
        }

        // ---- O += P @ V (V [s][d]: B frags via ldmatrix.trans) ----
        uint32_t rV = (lane & 7) + (((lane >> 3) & 1) << 3);
        uint32_t cV = ((lane >> 4) & 1) << 3;
#pragma unroll
        for (int kc = 0; kc < 4; kc++) {
#pragma unroll
            for (int p = 0; p < 4; p++) {
                uint32_t b0, b1, b2, b3;
                ldsm4t(b0, b1, b2, b3,
                       sVt + ((((uint32_t)(kc << 4) + rV) * AT_PAD + (uint32_t)(p << 4) + cV) << 1));
                mma_f16(oa[2*p][0], oa[2*p][1], oa[2*p][2], oa[2*p][3],
                        pa[kc][0], pa[kc][1], pa[kc][2], pa[kc][3], b0, b1);
                mma_f16(oa[2*p+1][0], oa[2*p+1][1], oa[2*p+1][2], oa[2*p+1][3],
                        pa[kc][0], pa[kc][1], pa[kc][2], pa[kc][3], b2, b3);
            }
        }
    }

    // ---- epilogue ----
    float i0 = 1.0f / l0, i1 = 1.0f / l1;
    int r0 = qt * 64 + (wid << 4) + (lane >> 2);
    __half* ob = outb + (size_t)(b * T_SEQ) * C_DIM + hh * 64;
#pragma unroll
    for (int nf = 0; nf < 8; nf++) {
        int c = (nf << 3) + ((lane & 3) << 1);
        __half2 h0 = __floats2half2_rn(oa[nf][0] * i0, oa[nf][1] * i0);
        __half2 h1 = __floats2half2_rn(oa[nf][2] * i1, oa[nf][3] * i1);
        *(__half2*)(ob + (size_t)r0 * C_DIM + c)       = h0;
        *(__half2*)(ob + (size_t)(r0 + 8) * C_DIM + c) = h1;
    }
}

// ---------------- launcher ----------------
extern "C" void kernel_launch(void* const* d_in, const int* in_sizes, int n_in,
                              void* d_out, int out_size)
{
    const int*   idx    = (const int*)  d_in[0];
    const float* tok    = (const float*)d_in[1];
    const float* pos    = (const float*)d_in[2];
    const float* ln1_s  = (const float*)d_in[3];
    const float* ln1_b  = (const float*)d_in[4];
    const float* Wq     = (const float*)d_in[5];
    const float* Wk     = (const float*)d_in[6];
    const float* Wv     = (const float*)d_in[7];
    const float* Wo     = (const float*)d_in[8];
    const float* bo     = (const float*)d_in[9];
    const float* ln2_s  = (const float*)d_in[10];
    const float* ln2_b  = (const float*)d_in[11];
    const float* W1     = (const float*)d_in[12];
    const float* b1     = (const float*)d_in[13];
    const float* W2     = (const float*)d_in[14];
    const float* b2     = (const float*)d_in[15];
    const float* lnf_s  = (const float*)d_in[16];
    const float* lnf_b  = (const float*)d_in[17];
    float* out = (float*)d_out;

    float *x;
    __half *qkvh, *hh, *ffh, *wph, *wth, *tokh;
    cudaGetSymbolAddress((void**)&x,     g_x);
    cudaGetSymbolAddress((void**)&qkvh,  g_qkvh);
    cudaGetSymbolAddress((void**)&hh,    g_hh);
    cudaGetSymbolAddress((void**)&ffh,   g_ffh);
    cudaGetSymbolAddress((void**)&wph,   g_wph);
    cudaGetSymbolAddress((void**)&wth,   g_wth);
    cudaGetSymbolAddress((void**)&tokh,  g_tokh);

    cudaFuncSetAttribute(hgemm<0>, cudaFuncAttributeMaxDynamicSharedMemorySize, GSMH);
    cudaFuncSetAttribute(hgemm<1>, cudaFuncAttributeMaxDynamicSharedMemorySize, GSMH);

    k_tokcvt<<<(V_SZ * C_DIM) / (256 * 8), 256>>>(tok, tokh);
    k_embed<<<M_ROWS, 256>>>(idx, tok, pos, x);

    for (int l = 0; l < L_NUM; l++) {
        // LN1 -> half
        k_ln<<<M_ROWS, 256>>>(x, ln1_s + l * C_DIM, ln1_b + l * C_DIM, hh);
        // pack qkv weights [3C, C] half
        k_packQKV<<<3 * 16 * 32, 256>>>(Wq, Wk, Wv, wph, l);
        // qkv = hh @ wph^T -> half
        hgemm<1><<<dim3(3072 / 128, M_ROWS / 128), 256, GSMH>>>(
            hh, wph, qkvh, nullptr, nullptr, 3072, C_DIM, 0);
        // tensor-core flash attention -> hh (half)
        k_attn<<<dim3(T_SEQ / 64, B_SZ * H_NUM), 128>>>(qkvh, hh);
        // x = x + hh @ Wo^T + bo
        k_wcvt<<<dim3(C_DIM / 32, C_DIM / 32), 256>>>(
            Wo + (size_t)l * C_DIM * C_DIM, wth, C_DIM, C_DIM);
        hgemm<0><<<dim3(C_DIM / 128, M_ROWS / 128), 256, GSMH>>>(
            hh, wth, x, bo + l * C_DIM, x, C_DIM, C_DIM, 0);
        // LN2 -> half
        k_ln<<<M_ROWS, 256>>>(x, ln2_s + l * C_DIM, ln2_b + l * C_DIM, hh);
        // ffh = relu(hh @ W1^T + b1) -> half
        k_wcvt<<<dim3(FF_DIM / 32, C_DIM / 32), 256>>>(
            W1 + (size_t)l * C_DIM * FF_DIM, wth, C_DIM, FF_DIM);
        hgemm<1><<<dim3(FF_DIM / 128, M_ROWS / 128), 256, GSMH>>>(
            hh, wth, ffh, b1 + l * FF_DIM, nullptr, FF_DIM, C_DIM, 1);
        // x = x + ffh @ W2^T + b2
        k_wcvt<<<dim3(C_DIM / 32, FF_DIM / 32), 256>>>(
            W2 + (size_t)l * FF_DIM * C_DIM, wth, FF_DIM, C_DIM);
        hgemm<0><<<dim3(C_DIM / 128, M_ROWS / 128), 256, GSMH>>>(
            ffh, wth, x, b2 + l * C_DIM, x, C_DIM, FF_DIM, 0);
    }

    // final LN + tied-embedding logits
    k_ln<<<M_ROWS, 256>>>(x, lnf_s, lnf_b, hh);
    hgemm<0><<<dim3(V_SZ / 128, M_ROWS / 128), 256, GSMH>>>(
        hh, tokh, out, nullptr, nullptr, V_SZ, C_DIM, 0);
}

// round 8
// speedup vs baseline: 2.2949x; 1.0578x over previous
#include <cuda_runtime.h>
#include <cuda_fp16.h>
#include <cstdint>
#include <math.h>

// ---------------- model constants ----------------
#define C_DIM   1024
#define H_NUM   16
#define D_HEAD  64
#define L_NUM   8
#define T_SEQ   1024
#define B_SZ    2
#define M_ROWS  (B_SZ * T_SEQ)      // 2048
#define FF_DIM  4096
#define V_SZ    32000

// ---------------- device scratch ----------------
__device__ __align__(256) float  g_x   [M_ROWS * C_DIM];            // residual (fp32)
__device__ __align__(256) __half g_qkvh[M_ROWS * 3 * C_DIM];        // qkv (half)
__device__ __align__(256) __half g_hh  [M_ROWS * C_DIM];            // LN out / attn out
__device__ __align__(256) __half g_ffh [M_ROWS * FF_DIM];           // relu FF out
__device__ __align__(256) __half g_wph [L_NUM * 3 * C_DIM * C_DIM]; // qkv W [N,K] all layers
__device__ __align__(256) __half g_woh [L_NUM * C_DIM * C_DIM];     // Wo half [K,N] all layers
__device__ __align__(256) __half g_w1h [L_NUM * C_DIM * FF_DIM];    // W1 half [K,N]
__device__ __align__(256) __half g_w2h [L_NUM * FF_DIM * C_DIM];    // W2 half [K,N]
__device__ __align__(256) __half g_tokh[V_SZ * C_DIM];              // tok [V,K]

// ============================================================
// helpers
// ============================================================
__device__ __forceinline__ uint32_t smem_u32(const void* p) {
    uint32_t a;
    asm("{ .reg .u64 t; cvta.to.shared.u64 t, %1; cvt.u32.u64 %0, t; }" : "=r"(a) : "l"(p));
    return a;
}
__device__ __forceinline__ void cpa16(uint32_t dst, const void* src) {
    asm volatile("cp.async.cg.shared.global [%0], [%1], 16;" :: "r"(dst), "l"(src));
}
__device__ __forceinline__ void ldsm4(uint32_t& r0, uint32_t& r1, uint32_t& r2, uint32_t& r3,
                                      uint32_t a) {
    asm volatile("ldmatrix.sync.aligned.m8n8.x4.shared.b16 {%0,%1,%2,%3}, [%4];"
        : "=r"(r0), "=r"(r1), "=r"(r2), "=r"(r3) : "r"(a));
}
__device__ __forceinline__ void ldsm4t(uint32_t& r0, uint32_t& r1, uint32_t& r2, uint32_t& r3,
                                       uint32_t a) {
    asm volatile("ldmatrix.sync.aligned.m8n8.x4.trans.shared.b16 {%0,%1,%2,%3}, [%4];"
        : "=r"(r0), "=r"(r1), "=r"(r2), "=r"(r3) : "r"(a));
}
__device__ __forceinline__ void mma_f16(float& c0, float& c1, float& c2, float& c3,
                                        uint32_t a0, uint32_t a1, uint32_t a2, uint32_t a3,
                                        uint32_t b0, uint32_t b1) {
    asm volatile("mma.sync.aligned.m16n8k16.row.col.f32.f16.f16.f32 "
        "{%0,%1,%2,%3}, {%4,%5,%6,%7}, {%8,%9}, {%0,%1,%2,%3};"
        : "+f"(c0), "+f"(c1), "+f"(c2), "+f"(c3)
        : "r"(a0), "r"(a1), "r"(a2), "r"(a3), "r"(b0), "r"(b1));
}

// ============================================================
// FP16 mma.sync GEMM: C[M,N] = A[M,K] @ B
//   MT:   CTA M-tile (128 or 64); N-tile fixed 128. 256 threads, 8 warps (2x4).
//   TRB=1: B stored [N,K] (A @ B^T), ldsm non-trans.
//   TRB=0: B stored [K,N] natural,  ldsm trans.
//   OUTH=1: half out (+bias)(+relu). OUTH=0: fp32 out (+bias)(+res).
// ============================================================
#define ROWH  40        // A / B-NK row pitch (32 + 8 pad halves)
#define ROWB  136       // B-KN row pitch (128 + 8 pad halves)

template<int MT, int OUTH, int TRB>
__global__ __launch_bounds__(256, MT == 64 ? 3 : 2)
void hgemm(const __half* __restrict__ A, const __half* __restrict__ B,
           void* __restrict__ Cout, const float* __restrict__ bias,
           const float* __restrict__ res, int N, int K, int relu)
{
    constexpr int MF      = MT / 32;                       // m-frags per warp
    constexpr int A_TILE  = MT * ROWH;                     // halves
    constexpr int B_TILE  = TRB ? 128 * ROWH : 32 * ROWB;  // halves
    constexpr int STAGE_B = (A_TILE + B_TILE) * 2;         // bytes

    extern __shared__ __half smh[];
    uint32_t sbase = smem_u32(smh);
    int tid  = threadIdx.x;
    int wid  = tid >> 5;
    int lane = tid & 31;
    int wm   = wid >> 2;          // 0..1
    int wn   = wid & 3;           // 0..3
    int bm = blockIdx.y * MT;
    int bn = blockIdx.x << 7;

    const __half* Ag = A + (size_t)bm * K;
    int NC = K >> 5;

    float acc[MF][4][4];
#pragma unroll
    for (int mf = 0; mf < MF; mf++)
#pragma unroll
        for (int nf = 0; nf < 4; nf++)
#pragma unroll
            for (int k = 0; k < 4; k++) acc[mf][nf][k] = 0.f;

    auto load_tile = [&](int ch, int stage) {
        int k0 = ch << 5;
        uint32_t so = sbase + (uint32_t)stage * STAGE_B;
        uint32_t bo = so + (uint32_t)A_TILE * 2u;
#pragma unroll
        for (int i = 0; i < MT / 64; i++) {                // A: MT rows x 32 k
            int id = tid + (i << 8);
            int r = id >> 2, c = (id & 3) << 3;
            cpa16(so + ((uint32_t)(r * ROWH + c) << 1), Ag + (size_t)r * K + k0 + c);
        }
        if (TRB) {                                         // B: 128 n-rows x 32 k
            const __half* Bg = B + (size_t)bn * K;
#pragma unroll
            for (int i = 0; i < 2; i++) {
                int id = tid + (i << 8);
                int r = id >> 2, c = (id & 3) << 3;
                cpa16(bo + ((uint32_t)(r * ROWH + c) << 1), Bg + (size_t)r * K + k0 + c);
            }
        } else {                                           // B: 32 k-rows x 128 n
#pragma unroll
            for (int i = 0; i < 2; i++) {
                int id = tid + (i << 8);
                int r = id >> 4, c = (id & 15) << 3;
                cpa16(bo + ((uint32_t)(r * ROWB + c) << 1),
                      B + (size_t)(k0 + r) * N + bn + c);
            }
        }
    };

    load_tile(0, 0);
    asm volatile("cp.async.commit_group;");

    uint32_t rA = (uint32_t)(wm * (MT / 2)) + (lane & 7) + (((lane >> 3) & 1) << 3);
    uint32_t kA = ((lane >> 4) & 1) << 3;
    // TRB=1 B-frag coords
    uint32_t rB = (uint32_t)(wn << 5) + (lane & 7) + (((lane >> 4) & 1) << 3);
    uint32_t kB = ((lane >> 3) & 1) << 3;
    // TRB=0 B-frag coords (trans)
    uint32_t rBt = (lane & 7) + (((lane >> 3) & 1) << 3);
    uint32_t cBt = (uint32_t)(wn << 5) + (((lane >> 4) & 1) << 3);

    for (int ch = 0; ch < NC; ch++) {
        if (ch > 0) __syncthreads();
        if (ch + 1 < NC) load_tile(ch + 1, (ch + 1) & 1);
        asm volatile("cp.async.commit_group;");
        asm volatile("cp.async.wait_group 1;");
        __syncthreads();

        uint32_t sA = sbase + (uint32_t)(ch & 1) * STAGE_B;
        uint32_t sB = sA + (uint32_t)A_TILE * 2u;
#pragma unroll
        for (int ks = 0; ks < 2; ks++) {
            uint32_t af[MF][4], bf[4][2];
            uint32_t kofs = (uint32_t)(ks << 4);
#pragma unroll
            for (int mf = 0; mf < MF; mf++) {
                uint32_t a = sA + (((rA + (uint32_t)(mf << 4)) * ROWH + kA + kofs) << 1);
                ldsm4(af[mf][0], af[mf][1], af[mf][2], af[mf][3], a);
            }
            if (TRB) {
#pragma unroll
                for (int p = 0; p < 2; p++) {
                    uint32_t a = sB + (((rB + (uint32_t)(p << 4)) * ROWH + kB + kofs) << 1);
                    ldsm4(bf[2 * p][0], bf[2 * p][1], bf[2 * p + 1][0], bf[2 * p + 1][1], a);
                }
            } else {
#pragma unroll
                for (int p = 0; p < 2; p++) {
                    uint32_t a = sB + (((kofs + rBt) * ROWB + cBt + (uint32_t)(p << 4)) << 1);
                    ldsm4t(bf[2 * p][0], bf[2 * p][1], bf[2 * p + 1][0], bf[2 * p + 1][1], a);
                }
            }
#pragma unroll
            for (int mf = 0; mf < MF; mf++)
#pragma unroll
                for (int nf = 0; nf < 4; nf++)
                    mma_f16(acc[mf][nf][0], acc[mf][nf][1], acc[mf][nf][2], acc[mf][nf][3],
                            af[mf][0], af[mf][1], af[mf][2], af[mf][3],
                            bf[nf][0], bf[nf][1]);
        }
    }

    // ---- epilogue ----
    int row0 = bm + wm * (MT / 2) + (lane >> 2);
    int col0 = bn + (wn << 5) + ((lane & 3) << 1);
#pragma unroll
    for (int mf = 0; mf < MF; mf++) {
#pragma unroll
        for (int half_ = 0; half_ < 2; half_++) {
            int row = row0 + (mf << 4) + half_ * 8;
#pragma unroll
            for (int nf = 0; nf < 4; nf++) {
                float vx = acc[mf][nf][half_ * 2 + 0];
                float vy = acc[mf][nf][half_ * 2 + 1];
                int c = (nf << 3);
                if (bias) {
                    vx += bias[col0 + c];
                    vy += bias[col0 + c + 1];
                }
                if (OUTH) {
                    if (relu) { vx = fmaxf(vx, 0.f); vy = fmaxf(vy, 0.f); }
                    __half2 hv = __floats2half2_rn(vx, vy);
                    *(__half2*)((__half*)Cout + (size_t)row * N + col0 + c) = hv;
                } else {
                    if (res) {
                        const float* rp = res + (size_t)row * N + col0 + c;
                        float2 r2 = *(const float2*)rp;
                        vx += r2.x; vy += r2.y;
                    }
                    float2 v; v.x = vx; v.y = vy;
                    *(float2*)((float*)Cout + (size_t)row * N + col0 + c) = v;
                }
            }
        }
    }
}

// ---------------- embedding ----------------
__global__ void k_embed(const int* __restrict__ idx,
                        const float* __restrict__ tok,
                        const float* __restrict__ pos,
                        float* __restrict__ x)
{
    int m = blockIdx.x;
    int c = threadIdx.x * 4;
    int t = m & (T_SEQ - 1);
    int v = idx[m];
    float4 a = *(const float4*)(tok + (size_t)v * C_DIM + c);
    float4 p = *(const float4*)(pos + (size_t)t * C_DIM + c);
    a.x += p.x; a.y += p.y; a.z += p.z; a.w += p.w;
    *(float4*)(x + (size_t)m * C_DIM + c) = a;
}

// ---------------- layernorm: fp32 in -> fp16 out ----------------
__global__ void k_ln(const float* __restrict__ x,
                     const float* __restrict__ sc,
                     const float* __restrict__ bi,
                     __half* __restrict__ out)
{
    int m = blockIdx.x;
    int tid = threadIdx.x;                 // 256 threads
    int c = tid * 4;
    float4 v = *(const float4*)(x + (size_t)m * C_DIM + c);
    float s = v.x + v.y + v.z + v.w;
    float q = v.x*v.x + v.y*v.y + v.z*v.z + v.w*v.w;

    __shared__ float rs[8], rq[8];
#pragma unroll
    for (int o = 16; o > 0; o >>= 1) {
        s += __shfl_xor_sync(0xffffffffu, s, o);
        q += __shfl_xor_sync(0xffffffffu, q, o);
    }
    if ((tid & 31) == 0) { rs[tid >> 5] = s; rq[tid >> 5] = q; }
    __syncthreads();
    float sum = 0.f, sq = 0.f;
#pragma unroll
    for (int w = 0; w < 8; w++) { sum += rs[w]; sq += rq[w]; }

    float mu = sum * (1.0f / C_DIM);
    float var = sq * (1.0f / C_DIM) - mu * mu;
    float rstd = rsqrtf(var + 1e-5f);

    float4 svv = *(const float4*)(sc + c);
    float4 bvv = *(const float4*)(bi + c);
    __half2 p0 = __floats2half2_rn((v.x - mu) * rstd * svv.x + bvv.x,
                                   (v.y - mu) * rstd * svv.y + bvv.y);
    __half2 p1 = __floats2half2_rn((v.z - mu) * rstd * svv.z + bvv.z,
                                   (v.w - mu) * rstd * svv.w + bvv.w);
    uint2 st;
    st.x = *(uint32_t*)&p0;
    st.y = *(uint32_t*)&p1;
    *(uint2*)(out + (size_t)m * C_DIM + c) = st;
}

// ---------------- pack qkv weights ALL layers -> [L][3C, C] half ----------------
__global__ __launch_bounds__(256)
void k_packQKV(const float* __restrict__ Wq, const float* __restrict__ Wk,
               const float* __restrict__ Wv, __half* __restrict__ out)
{
    __shared__ float t[32][65];
    int b  = blockIdx.x;
    int l  = b / 1536;
    b -= l * 1536;
    int kb = b & 31;
    int hh = (b >> 5) & 15;
    int s  = b >> 9;
    const float* W = (s == 0) ? Wq : ((s == 1) ? Wk : Wv);
    const float* Wb = W + ((size_t)l * H_NUM + hh) * C_DIM * D_HEAD + (size_t)(kb << 5) * D_HEAD;
    int tid = threadIdx.x;
#pragma unroll
    for (int i = 0; i < 8; i++) {
        int idx = tid + (i << 8);
        int r = idx >> 6, d = idx & 63;
        t[r][d] = Wb[(size_t)r * D_HEAD + d];
    }
    __syncthreads();
    __half* outl = out + (size_t)l * 3 * C_DIM * C_DIM;
    int n0 = s * 1024 + hh * 64;
#pragma unroll
    for (int i = 0; i < 8; i++) {
        int idx = tid + (i << 8);
        int d = idx >> 5, kk = idx & 31;
        outl[(size_t)(n0 + d) * C_DIM + (kb << 5) + kk] = __float2half_rn(t[kk][d]);
    }
}

// ---------------- pure fp32 -> fp16 convert (layout preserved) ----------------
__global__ __launch_bounds__(256)
void k_cvt(const float* __restrict__ in, __half* __restrict__ out)
{
    size_t i = ((size_t)blockIdx.x * 256 + threadIdx.x) * 8;
    float4 a = *(const float4*)(in + i);
    float4 b = *(const float4*)(in + i + 4);
    __half2 h0 = __floats2half2_rn(a.x, a.y);
    __half2 h1 = __floats2half2_rn(a.z, a.w);
    __half2 h2 = __floats2half2_rn(b.x, b.y);
    __half2 h3 = __floats2half2_rn(b.z, b.w);
    uint4 st;
    st.x = *(uint32_t*)&h0; st.y = *(uint32_t*)&h1;
    st.z = *(uint32_t*)&h2; st.w = *(uint32_t*)&h3;
    *(uint4*)(out + i) = st;
}

// ============================================================
// Tensor-core causal flash attention (unchanged from round 7).
// ============================================================
#define AT_PAD  72
#define AT_TILEB (64 * AT_PAD * 2)

__global__ __launch_bounds__(128)
void k_attn(const __half* __restrict__ qkvh, __half* __restrict__ outb)
{
    __shared__ __half Qs[64][AT_PAD];
    __shared__ __half Ks[2][64][AT_PAD];
    __shared__ __half Vs[2][64][AT_PAD];

    int qt = blockIdx.x;
    int b  = blockIdx.y >> 4;
    int hh = blockIdx.y & 15;
    int tid = threadIdx.x;
    int wid = tid >> 5, lane = tid & 31;

    const __half* qp = qkvh + ((size_t)(b * T_SEQ + qt * 64)) * 3072 + hh * 64;
    const __half* kp = qkvh + ((size_t)(b * T_SEQ)) * 3072 + 1024 + hh * 64;
    const __half* vp = kp + 1024;

    uint32_t sQ = smem_u32(Qs);
    uint32_t sK = smem_u32(Ks);
    uint32_t sV = smem_u32(Vs);

#pragma unroll
    for (int i = 0; i < 4; i++) {
        int id = tid + (i << 7);
        int r = id >> 3, c = (id & 7) << 3;
        uint32_t off = (uint32_t)(r * AT_PAD + c) << 1;
        cpa16(sQ + off, qp + (size_t)r * 3072 + c);
        cpa16(sK + off, kp + (size_t)r * 3072 + c);
        cpa16(sV + off, vp + (size_t)r * 3072 + c);
    }
    asm volatile("cp.async.commit_group;");

    uint32_t qf[4][4];
    float oa[8][4];
    float m0 = -1e30f, m1 = -1e30f, l0 = 0.f, l1 = 0.f;
#pragma unroll
    for (int i = 0; i < 8; i++) { oa[i][0] = oa[i][1] = oa[i][2] = oa[i][3] = 0.f; }

    for (int kt = 0; kt <= qt; kt++) {
        if (kt > 0) __syncthreads();
        if (kt < qt) {
            uint32_t st = (uint32_t)((kt + 1) & 1) * AT_TILEB;
#pragma unroll
            for (int i = 0; i < 4; i++) {
                int id = tid + (i << 7);
                int r = id >> 3, c = (id & 7) << 3;
                uint32_t off = (uint32_t)(r * AT_PAD + c) << 1;
                cpa16(sK + st + off, kp + (size_t)((kt + 1) * 64 + r) * 3072 + c);
                cpa16(sV + st + off, vp + (size_t)((kt + 1) * 64 + r) * 3072 + c);
            }
        }
        asm volatile("cp.async.commit_group;");
        asm volatile("cp.async.wait_group 1;");
        __syncthreads();

        if (kt == 0) {
            uint32_t rAq = (uint32_t)(wid << 4) + (lane & 7) + (((lane >> 3) & 1) << 3);
#pragma unroll
            for (int kc = 0; kc < 4; kc++) {
                uint32_t kAq = (((lane >> 4) & 1) << 3) + (kc << 4);
                ldsm4(qf[kc][0], qf[kc][1], qf[kc][2], qf[kc][3],
                      sQ + ((rAq * AT_PAD + kAq) << 1));
            }
        }

        uint32_t sKt = sK + (uint32_t)(kt & 1) * AT_TILEB;
        uint32_t sVt = sV + (uint32_t)(kt & 1) * AT_TILEB;

        float s[8][4];
#pragma unroll
        for (int i = 0; i < 8; i++) { s[i][0] = s[i][1] = s[i][2] = s[i][3] = 0.f; }
        uint32_t rBk = (lane & 7) + (((lane >> 4) & 1) << 3);
        uint32_t kBo = ((lane >> 3) & 1) << 3;
#pragma unroll
        for (int kc = 0; kc < 4; kc++) {
#pragma unroll
            for (int p = 0; p < 4; p++) {
                uint32_t b0, b1, b2, b3;
                ldsm4(b0, b1, b2, b3,
                      sKt + (((rBk + (uint32_t)(p << 4)) * AT_PAD + kBo + (kc << 4)) << 1));
                mma_f16(s[2*p][0], s[2*p][1], s[2*p][2], s[2*p][3],
                        qf[kc][0], qf[kc][1], qf[kc][2], qf[kc][3], b0, b1);
                mma_f16(s[2*p+1][0], s[2*p+1][1], s[2*p+1][2], s[2*p+1][3],
                        qf[kc][0], qf[kc][1], qf[kc][2], qf[kc][3], b2, b3);
            }
        }
#pragma unroll
        for (int i = 0; i < 8; i++) {
            s[i][0] *= 0.125f; s[i][1] *= 0.125f; s[i][2] *= 0.125f; s[i][3] *= 0.125f;
        }
        if (kt == qt) {
            int r0 = (wid << 4) + (lane >> 2);
#pragma unroll
            for (int nf = 0; nf < 8; nf++) {
                int c0 = (nf << 3) + ((lane & 3) << 1);
                if (c0     > r0)     s[nf][0] = -1e30f;
                if (c0 + 1 > r0)     s[nf][1] = -1e30f;
                if (c0     > r0 + 8) s[nf][2] = -1e30f;
                if (c0 + 1 > r0 + 8) s[nf][3] = -1e30f;
            }
        }

        float mx0 = s[0][0], mx1 = s[0][2];
#pragma unroll
        for (int nf = 0; nf < 8; nf++) {
            mx0 = fmaxf(mx0, fmaxf(s[nf][0], s[nf][1]));
            mx1 = fmaxf(mx1, fmaxf(s[nf][2], s[nf][3]));
        }
        mx0 = fmaxf(mx0, __shfl_xor_sync(0xffffffffu, mx0, 1));
        mx0 = fmaxf(mx0, __shfl_xor_sync(0xffffffffu, mx0, 2));
        mx1 = fmaxf(mx1, __shfl_xor_sync(0xffffffffu, mx1, 1));
        mx1 = fmaxf(mx1, __shfl_xor_sync(0xffffffffu, mx1, 2));
        float mn0 = fmaxf(m0, mx0), mn1 = fmaxf(m1, mx1);
        float cr0 = __expf(m0 - mn0), cr1 = __expf(m1 - mn1);
        float rs0 = 0.f, rs1 = 0.f;
        uint32_t pa[4][4];
#pragma unroll
        for (int nf = 0; nf < 8; nf++) {
            float p0 = __expf(s[nf][0] - mn0);
            float p1 = __expf(s[nf][1] - mn0);
            float p2 = __expf(s[nf][2] - mn1);
            float p3 = __expf(s[nf][3] - mn1);
            rs0 += p0 + p1; rs1 += p2 + p3;
            __half2 h01 = __floats2half2_rn(p0, p1);
            __half2 h23 = __floats2half2_rn(p2, p3);
            int kc = nf >> 1, hi = (nf & 1) << 1;
            pa[kc][hi]     = *(uint32_t*)&h01;
            pa[kc][hi + 1] = *(uint32_t*)&h23;
        }
        rs0 += __shfl_xor_sync(0xffffffffu, rs0, 1);
        rs0 += __shfl_xor_sync(0xffffffffu, rs0, 2);
        rs1 += __shfl_xor_sync(0xffffffffu, rs1, 1);
        rs1 += __shfl_xor_sync(0xffffffffu, rs1, 2);
        l0 = l0 * cr0 + rs0; l1 = l1 * cr1 + rs1;
        m0 = mn0; m1 = mn1;
#pragma unroll
        for (int i = 0; i < 8; i++) {
            oa[i][0] *= cr0; oa[i][1] *= cr0; oa[i][2] *= cr1; oa[i][3] *= cr1;
        }

        uint32_t rV = (lane & 7) + (((lane >> 3) & 1) << 3);
        uint32_t cV = ((lane >> 4) & 1) << 3;
#pragma unroll
        for (int kc = 0; kc < 4; kc++) {
#pragma unroll
            for (int p = 0; p < 4; p++) {
                uint32_t b0, b1, b2, b3;
                ldsm4t(b0, b1, b2, b3,
                       sVt + ((((uint32_t)(kc << 4) + rV) * AT_PAD + (uint32_t)(p << 4) + cV) << 1));
                mma_f16(oa[2*p][0], oa[2*p][1], oa[2*p][2], oa[2*p][3],
                        pa[kc][0], pa[kc][1], pa[kc][2], pa[kc][3], b0, b1);
                mma_f16(oa[2*p+1][0], oa[2*p+1][1], oa[2*p+1][2], oa[2*p+1][3],
                        pa[kc][0], pa[kc][1], pa[kc][2], pa[kc][3], b2, b3);
            }
        }
    }

    float i0 = 1.0f / l0, i1 = 1.0f / l1;
    int r0 = qt * 64 + (wid << 4) + (lane >> 2);
    __half* ob = outb + (size_t)(b * T_SEQ) * C_DIM + hh * 64;
#pragma unroll
    for (int nf = 0; nf < 8; nf++) {
        int c = (nf << 3) + ((lane & 3) << 1);
        __half2 h0 = __floats2half2_rn(oa[nf][0] * i0, oa[nf][1] * i0);
        __half2 h1 = __floats2half2_rn(oa[nf][2] * i1, oa[nf][3] * i1);
        *(__half2*)(ob + (size_t)r0 * C_DIM + c)       = h0;
        *(__half2*)(ob + (size_t)(r0 + 8) * C_DIM + c) = h1;
    }
}

// ---------------- smem sizes per instantiation ----------------
#define GSM_128_NK  ((128 * ROWH + 128 * ROWH) * 2 * 2)   // 40960
#define GSM_128_KN  ((128 * ROWH + 32 * ROWB) * 2 * 2)    // 37888
#define GSM_64_KN   ((64 * ROWH + 32 * ROWB) * 2 * 2)     // 27648

// ---------------- launcher ----------------
extern "C" void kernel_launch(void* const* d_in, const int* in_sizes, int n_in,
                              void* d_out, int out_size)
{
    const int*   idx    = (const int*)  d_in[0];
    const float* tok    = (const float*)d_in[1];
    const float* pos    = (const float*)d_in[2];
    const float* ln1_s  = (const float*)d_in[3];
    const float* ln1_b  = (const float*)d_in[4];
    const float* Wq     = (const float*)d_in[5];
    const float* Wk     = (const float*)d_in[6];
    const float* Wv     = (const float*)d_in[7];
    const float* Wo     = (const float*)d_in[8];
    const float* bo     = (const float*)d_in[9];
    const float* ln2_s  = (const float*)d_in[10];
    const float* ln2_b  = (const float*)d_in[11];
    const float* W1     = (const float*)d_in[12];
    const float* b1     = (const float*)d_in[13];
    const float* W2     = (const float*)d_in[14];
    const float* b2     = (const float*)d_in[15];
    const float* lnf_s  = (const float*)d_in[16];
    const float* lnf_b  = (const float*)d_in[17];
    float* out = (float*)d_out;

    float *x;
    __half *qkvh, *hh, *ffh, *wph, *woh, *w1h, *w2h, *tokh;
    cudaGetSymbolAddress((void**)&x,     g_x);
    cudaGetSymbolAddress((void**)&qkvh,  g_qkvh);
    cudaGetSymbolAddress((void**)&hh,    g_hh);
    cudaGetSymbolAddress((void**)&ffh,   g_ffh);
    cudaGetSymbolAddress((void**)&wph,   g_wph);
    cudaGetSymbolAddress((void**)&woh,   g_woh);
    cudaGetSymbolAddress((void**)&w1h,   g_w1h);
    cudaGetSymbolAddress((void**)&w2h,   g_w2h);
    cudaGetSymbolAddress((void**)&tokh,  g_tokh);

    // ---- one-time per call: weight conversion (layout preserved / pack) ----
    k_tokcvt_dummy:;
    k_cvt<<<(V_SZ * C_DIM) / 2048, 256>>>(tok, tokh);
    k_cvt<<<(L_NUM * C_DIM * C_DIM) / 2048, 256>>>(Wo, woh);
    k_cvt<<<(L_NUM * C_DIM * FF_DIM) / 2048, 256>>>(W1, w1h);
    k_cvt<<<(L_NUM * FF_DIM * C_DIM) / 2048, 256>>>(W2, w2h);
    k_packQKV<<<L_NUM * 1536, 256>>>(Wq, Wk, Wv, wph);
    k_embed<<<M_ROWS, 256>>>(idx, tok, pos, x);

    for (int l = 0; l < L_NUM; l++) {
        // LN1 -> half
        k_ln<<<M_ROWS, 256>>>(x, ln1_s + l * C_DIM, ln1_b + l * C_DIM, hh);
        // qkv = hh @ wph^T -> half
        hgemm<128,1,1><<<dim3(3072 / 128, M_ROWS / 128), 256, GSM_128_NK>>>(
            hh, wph + (size_t)l * 3 * C_DIM * C_DIM, qkvh, nullptr, nullptr, 3072, C_DIM, 0);
        // tensor-core flash attention -> hh
        k_attn<<<dim3(T_SEQ / 64, B_SZ * H_NUM), 128>>>(qkvh, hh);
        // x = x + hh @ Wo + bo   (Wo [K,N], MT=64 for grid fill)
        hgemm<64,0,0><<<dim3(C_DIM / 128, M_ROWS / 64), 256, GSM_64_KN>>>(
            hh, woh + (size_t)l * C_DIM * C_DIM, x, bo + l * C_DIM, x, C_DIM, C_DIM, 0);
        // LN2 -> half
        k_ln<<<M_ROWS, 256>>>(x, ln2_s + l * C_DIM, ln2_b + l * C_DIM, hh);
        // ffh = relu(hh @ W1 + b1) -> half  (W1 [K,N])
        hgemm<128,1,0><<<dim3(FF_DIM / 128, M_ROWS / 128), 256, GSM_128_KN>>>(
            hh, w1h + (size_t)l * C_DIM * FF_DIM, ffh, b1 + l * FF_DIM, nullptr, FF_DIM, C_DIM, 1);
        // x = x + ffh @ W2 + b2  (W2 [K,N], MT=64)
        hgemm<64,0,0><<<dim3(C_DIM / 128, M_ROWS / 64), 256, GSM_64_KN>>>(
            ffh, w2h + (size_t)l * FF_DIM * C_DIM, x, b2 + l * C_DIM, x, C_DIM, FF_DIM, 0);
    }

    // final LN + tied-embedding logits (tok [V,K] -> TRB=1)
    k_ln<<<M_ROWS, 256>>>(x, lnf_s, lnf_b, hh);
    hgemm<128,0,1><<<dim3(V_SZ / 128, M_ROWS / 128), 256, GSM_128_NK>>>(
        hh, tokh, out, nullptr, nullptr, V_SZ, C_DIM, 0);
}

// round 9
// speedup vs baseline: 2.5901x; 1.1287x over previous
#include <cuda_runtime.h>
#include <cuda_fp16.h>
#include <cstdint>
#include <math.h>

// ---------------- model constants ----------------
#define C_DIM   1024
#define H_NUM   16
#define D_HEAD  64
#define L_NUM   8
#define T_SEQ   1024
#define B_SZ    2
#define M_ROWS  (B_SZ * T_SEQ)      // 2048
#define FF_DIM  4096
#define V_SZ    32000

// ---------------- device scratch ----------------
__device__ __align__(256) float  g_x   [M_ROWS * C_DIM];            // residual (fp32)
__device__ __align__(256) __half g_qkvh[M_ROWS * 3 * C_DIM];        // qkv (half)
__device__ __align__(256) __half g_hh  [M_ROWS * C_DIM];            // LN out / attn out
__device__ __align__(256) __half g_ffh [M_ROWS * FF_DIM];           // relu FF out
__device__ __align__(256) __half g_wph [L_NUM * 3 * C_DIM * C_DIM]; // qkv W [N,K] all layers
__device__ __align__(256) __half g_woh [L_NUM * C_DIM * C_DIM];     // Wo half [K,N]
__device__ __align__(256) __half g_w1h [L_NUM * C_DIM * FF_DIM];    // W1 half [K,N]
__device__ __align__(256) __half g_w2h [L_NUM * FF_DIM * C_DIM];    // W2 half [K,N]
__device__ __align__(256) __half g_tokh[V_SZ * C_DIM];              // tok [V,K]

// ============================================================
// helpers
// ============================================================
__device__ __forceinline__ uint32_t smem_u32(const void* p) {
    uint32_t a;
    asm("{ .reg .u64 t; cvta.to.shared.u64 t, %1; cvt.u32.u64 %0, t; }" : "=r"(a) : "l"(p));
    return a;
}
__device__ __forceinline__ void cpa16(uint32_t dst, const void* src) {
    asm volatile("cp.async.cg.shared.global [%0], [%1], 16;" :: "r"(dst), "l"(src));
}
__device__ __forceinline__ void ldsm4(uint32_t& r0, uint32_t& r1, uint32_t& r2, uint32_t& r3,
                                      uint32_t a) {
    asm volatile("ldmatrix.sync.aligned.m8n8.x4.shared.b16 {%0,%1,%2,%3}, [%4];"
        : "=r"(r0), "=r"(r1), "=r"(r2), "=r"(r3) : "r"(a));
}
__device__ __forceinline__ void ldsm4t(uint32_t& r0, uint32_t& r1, uint32_t& r2, uint32_t& r3,
                                       uint32_t a) {
    asm volatile("ldmatrix.sync.aligned.m8n8.x4.trans.shared.b16 {%0,%1,%2,%3}, [%4];"
        : "=r"(r0), "=r"(r1), "=r"(r2), "=r"(r3) : "r"(a));
}
__device__ __forceinline__ void mma_f16(float& c0, float& c1, float& c2, float& c3,
                                        uint32_t a0, uint32_t a1, uint32_t a2, uint32_t a3,
                                        uint32_t b0, uint32_t b1) {
    asm volatile("mma.sync.aligned.m16n8k16.row.col.f32.f16.f16.f32 "
        "{%0,%1,%2,%3}, {%4,%5,%6,%7}, {%8,%9}, {%0,%1,%2,%3};"
        : "+f"(c0), "+f"(c1), "+f"(c2), "+f"(c3)
        : "r"(a0), "r"(a1), "r"(a2), "r"(a3), "r"(b0), "r"(b1));
}

// ============================================================
// FP16 mma.sync GEMM: C[M,N] = A[M,K] @ B.  BK=64.
//   MT:   CTA M-tile (128 or 64); N-tile fixed 128. 256 threads, 8 warps (2x4).
//   TRB=1: B stored [N,K] (A @ B^T), ldsm non-trans.
//   TRB=0: B stored [K,N] natural,  ldsm trans.
//   OUTH=1: half out (+bias)(+relu). OUTH=0: fp32 out (+bias)(+res).
// ============================================================
#define ROWH  72        // A / B-NK row pitch (64 + 8 pad halves; 144B, stride%128B=16 -> conflict-free)
#define ROWB  136       // B-KN row pitch (128 + 8 pad halves; 272B)

template<int MT, int OUTH, int TRB>
__global__ __launch_bounds__(256, MT == 64 ? 3 : 2)
void hgemm(const __half* __restrict__ A, const __half* __restrict__ B,
           void* __restrict__ Cout, const float* __restrict__ bias,
           const float* __restrict__ res, int N, int K, int relu)
{
    constexpr int MF      = MT / 32;                       // m-frags per warp
    constexpr int A_TILE  = MT * ROWH;                     // halves
    constexpr int B_TILE  = TRB ? 128 * ROWH : 64 * ROWB;  // halves
    constexpr int STAGE_B = (A_TILE + B_TILE) * 2;         // bytes

    extern __shared__ __half smh[];
    uint32_t sbase = smem_u32(smh);
    int tid  = threadIdx.x;
    int wid  = tid >> 5;
    int lane = tid & 31;
    int wm   = wid >> 2;          // 0..1
    int wn   = wid & 3;           // 0..3
    int bm = blockIdx.y * MT;
    int bn = blockIdx.x << 7;

    const __half* Ag = A + (size_t)bm * K;
    int NC = K >> 6;

    float acc[MF][4][4];
#pragma unroll
    for (int mf = 0; mf < MF; mf++)
#pragma unroll
        for (int nf = 0; nf < 4; nf++)
#pragma unroll
            for (int k = 0; k < 4; k++) acc[mf][nf][k] = 0.f;

    auto load_tile = [&](int ch, int stage) {
        int k0 = ch << 6;
        uint32_t so = sbase + (uint32_t)stage * STAGE_B;
        uint32_t bo = so + (uint32_t)A_TILE * 2u;
#pragma unroll
        for (int i = 0; i < MT / 32; i++) {                // A: MT rows x 64 k
            int id = tid + (i << 8);
            int r = id >> 3, c = (id & 7) << 3;
            cpa16(so + ((uint32_t)(r * ROWH + c) << 1), Ag + (size_t)r * K + k0 + c);
        }
        if (TRB) {                                         // B: 128 n-rows x 64 k
            const __half* Bg = B + (size_t)bn * K;
#pragma unroll
            for (int i = 0; i < 4; i++) {
                int id = tid + (i << 8);
                int r = id >> 3, c = (id & 7) << 3;
                cpa16(bo + ((uint32_t)(r * ROWH + c) << 1), Bg + (size_t)r * K + k0 + c);
            }
        } else {                                           // B: 64 k-rows x 128 n
#pragma unroll
            for (int i = 0; i < 4; i++) {
                int id = tid + (i << 8);
                int r = id >> 4, c = (id & 15) << 3;
                cpa16(bo + ((uint32_t)(r * ROWB + c) << 1),
                      B + (size_t)(k0 + r) * N + bn + c);
            }
        }
    };

    load_tile(0, 0);
    asm volatile("cp.async.commit_group;");

    uint32_t rA = (uint32_t)(wm * (MT / 2)) + (lane & 7) + (((lane >> 3) & 1) << 3);
    uint32_t kA = ((lane >> 4) & 1) << 3;
    // TRB=1 B-frag coords
    uint32_t rB = (uint32_t)(wn << 5) + (lane & 7) + (((lane >> 4) & 1) << 3);
    uint32_t kB = ((lane >> 3) & 1) << 3;
    // TRB=0 B-frag coords (trans)
    uint32_t rBt = (lane & 7) + (((lane >> 3) & 1) << 3);
    uint32_t cBt = (uint32_t)(wn << 5) + (((lane >> 4) & 1) << 3);

    for (int ch = 0; ch < NC; ch++) {
        if (ch > 0) __syncthreads();
        if (ch + 1 < NC) load_tile(ch + 1, (ch + 1) & 1);
        asm volatile("cp.async.commit_group;");
        asm volatile("cp.async.wait_group 1;");
        __syncthreads();

        uint32_t sA = sbase + (uint32_t)(ch & 1) * STAGE_B;
        uint32_t sB = sA + (uint32_t)A_TILE * 2u;
#pragma unroll
        for (int ks = 0; ks < 4; ks++) {
            uint32_t af[MF][4], bf[4][2];
            uint32_t kofs = (uint32_t)(ks << 4);
#pragma unroll
            for (int mf = 0; mf < MF; mf++) {
                uint32_t a = sA + (((rA + (uint32_t)(mf << 4)) * ROWH + kA + kofs) << 1);
                ldsm4(af[mf][0], af[mf][1], af[mf][2], af[mf][3], a);
            }
            if (TRB) {
#pragma unroll
                for (int p = 0; p < 2; p++) {
                    uint32_t a = sB + (((rB + (uint32_t)(p << 4)) * ROWH + kB + kofs) << 1);
                    ldsm4(bf[2 * p][0], bf[2 * p][1], bf[2 * p + 1][0], bf[2 * p + 1][1], a);
                }
            } else {
#pragma unroll
                for (int p = 0; p < 2; p++) {
                    uint32_t a = sB + (((kofs + rBt) * ROWB + cBt + (uint32_t)(p << 4)) << 1);
                    ldsm4t(bf[2 * p][0], bf[2 * p][1], bf[2 * p + 1][0], bf[2 * p + 1][1], a);
                }
            }
#pragma unroll
            for (int mf = 0; mf < MF; mf++)
#pragma unroll
                for (int nf = 0; nf < 4; nf++)
                    mma_f16(acc[mf][nf][0], acc[mf][nf][1], acc[mf][nf][2], acc[mf][nf][3],
                            af[mf][0], af[mf][1], af[mf][2], af[mf][3],
                            bf[nf][0], bf[nf][1]);
        }
    }

    // ---- epilogue ----
    int row0 = bm + wm * (MT / 2) + (lane >> 2);
    int col0 = bn + (wn << 5) + ((lane & 3) << 1);
#pragma unroll
    for (int mf = 0; mf < MF; mf++) {
#pragma unroll
        for (int half_ = 0; half_ < 2; half_++) {
            int row = row0 + (mf << 4) + half_ * 8;
#pragma unroll
            for (int nf = 0; nf < 4; nf++) {
                float vx = acc[mf][nf][half_ * 2 + 0];
                float vy = acc[mf][nf][half_ * 2 + 1];
                int c = (nf << 3);
                if (bias) {
                    vx += bias[col0 + c];
                    vy += bias[col0 + c + 1];
                }
                if (OUTH) {
                    if (relu) { vx = fmaxf(vx, 0.f); vy = fmaxf(vy, 0.f); }
                    __half2 hv = __floats2half2_rn(vx, vy);
                    *(__half2*)((__half*)Cout + (size_t)row * N + col0 + c) = hv;
                } else {
                    if (res) {
                        const float* rp = res + (size_t)row * N + col0 + c;
                        float2 r2 = *(const float2*)rp;
                        vx += r2.x; vy += r2.y;
                    }
                    float2 v; v.x = vx; v.y = vy;
                    *(float2*)((float*)Cout + (size_t)row * N + col0 + c) = v;
                }
            }
        }
    }
}

// ---------------- embedding ----------------
__global__ void k_embed(const int* __restrict__ idx,
                        const float* __restrict__ tok,
                        const float* __restrict__ pos,
                        float* __restrict__ x)
{
    int m = blockIdx.x;
    int c = threadIdx.x * 4;
    int t = m & (T_SEQ - 1);
    int v = idx[m];
    float4 a = *(const float4*)(tok + (size_t)v * C_DIM + c);
    float4 p = *(const float4*)(pos + (size_t)t * C_DIM + c);
    a.x += p.x; a.y += p.y; a.z += p.z; a.w += p.w;
    *(float4*)(x + (size_t)m * C_DIM + c) = a;
}

// ---------------- layernorm: fp32 in -> fp16 out ----------------
__global__ void k_ln(const float* __restrict__ x,
                     const float* __restrict__ sc,
                     const float* __restrict__ bi,
                     __half* __restrict__ out)
{
    int m = blockIdx.x;
    int tid = threadIdx.x;                 // 256 threads
    int c = tid * 4;
    float4 v = *(const float4*)(x + (size_t)m * C_DIM + c);
    float s = v.x + v.y + v.z + v.w;
    float q = v.x*v.x + v.y*v.y + v.z*v.z + v.w*v.w;

    __shared__ float rs[8], rq[8];
#pragma unroll
    for (int o = 16; o > 0; o >>= 1) {
        s += __shfl_xor_sync(0xffffffffu, s, o);
        q += __shfl_xor_sync(0xffffffffu, q, o);
    }
    if ((tid & 31) == 0) { rs[tid >> 5] = s; rq[tid >> 5] = q; }
    __syncthreads();
    float sum = 0.f, sq = 0.f;
#pragma unroll
    for (int w = 0; w < 8; w++) { sum += rs[w]; sq += rq[w]; }

    float mu = sum * (1.0f / C_DIM);
    float var = sq * (1.0f / C_DIM) - mu * mu;
    float rstd = rsqrtf(var + 1e-5f);

    float4 svv = *(const float4*)(sc + c);
    float4 bvv = *(const float4*)(bi + c);
    __half2 p0 = __floats2half2_rn((v.x - mu) * rstd * svv.x + bvv.x,
                                   (v.y - mu) * rstd * svv.y + bvv.y);
    __half2 p1 = __floats2half2_rn((v.z - mu) * rstd * svv.z + bvv.z,
                                   (v.w - mu) * rstd * svv.w + bvv.w);
    uint2 st;
    st.x = *(uint32_t*)&p0;
    st.y = *(uint32_t*)&p1;
    *(uint2*)(out + (size_t)m * C_DIM + c) = st;
}

// ---------------- pack qkv weights ALL layers -> [L][3C, C] half ----------------
__global__ __launch_bounds__(256)
void k_packQKV(const float* __restrict__ Wq, const float* __restrict__ Wk,
               const float* __restrict__ Wv, __half* __restrict__ out)
{
    __shared__ float t[32][65];
    int b  = blockIdx.x;
    int l  = b / 1536;
    b -= l * 1536;
    int kb = b & 31;
    int hh = (b >> 5) & 15;
    int s  = b >> 9;
    const float* W = (s == 0) ? Wq : ((s == 1) ? Wk : Wv);
    const float* Wb = W + ((size_t)l * H_NUM + hh) * C_DIM * D_HEAD + (size_t)(kb << 5) * D_HEAD;
    int tid = threadIdx.x;
#pragma unroll
    for (int i = 0; i < 8; i++) {
        int idx = tid + (i << 8);
        int r = idx >> 6, d = idx & 63;
        t[r][d] = Wb[(size_t)r * D_HEAD + d];
    }
    __syncthreads();
    __half* outl = out + (size_t)l * 3 * C_DIM * C_DIM;
    int n0 = s * 1024 + hh * 64;
#pragma unroll
    for (int i = 0; i < 8; i++) {
        int idx = tid + (i << 8);
        int d = idx >> 5, kk = idx & 31;
        outl[(size_t)(n0 + d) * C_DIM + (kb << 5) + kk] = __float2half_rn(t[kk][d]);
    }
}

// ---------------- pure fp32 -> fp16 convert (layout preserved) ----------------
__global__ __launch_bounds__(256)
void k_cvt(const float* __restrict__ in, __half* __restrict__ out)
{
    size_t i = ((size_t)blockIdx.x * 256 + threadIdx.x) * 8;
    float4 a = *(const float4*)(in + i);
    float4 b = *(const float4*)(in + i + 4);
    __half2 h0 = __floats2half2_rn(a.x, a.y);
    __half2 h1 = __floats2half2_rn(a.z, a.w);
    __half2 h2 = __floats2half2_rn(b.x, b.y);
    __half2 h3 = __floats2half2_rn(b.z, b.w);
    uint4 st;
    st.x = *(uint32_t*)&h0; st.y = *(uint32_t*)&h1;
    st.z = *(uint32_t*)&h2; st.w = *(uint32_t*)&h3;
    *(uint4*)(out + i) = st;
}

// ============================================================
// Tensor-core causal flash attention.
// ============================================================
#define AT_PAD  72
#define AT_TILEB (64 * AT_PAD * 2)

__global__ __launch_bounds__(128)
void k_attn(const __half* __restrict__ qkvh, __half* __restrict__ outb)
{
    __shared__ __half Qs[64][AT_PAD];
    __shared__ __half Ks[2][64][AT_PAD];
    __shared__ __half Vs[2][64][AT_PAD];

    int qt = blockIdx.x;
    int b  = blockIdx.y >> 4;
    int hh = blockIdx.y & 15;
    int tid = threadIdx.x;
    int wid = tid >> 5, lane = tid & 31;

    const __half* qp = qkvh + ((size_t)(b * T_SEQ + qt * 64)) * 3072 + hh * 64;
    const __half* kp = qkvh + ((size_t)(b * T_SEQ)) * 3072 + 1024 + hh * 64;
    const __half* vp = kp + 1024;

    uint32_t sQ = smem_u32(Qs);
    uint32_t sK = smem_u32(Ks);
    uint32_t sV = smem_u32(Vs);

#pragma unroll
    for (int i = 0; i < 4; i++) {
        int id = tid + (i << 7);
        int r = id >> 3, c = (id & 7) << 3;
        uint32_t off = (uint32_t)(r * AT_PAD + c) << 1;
        cpa16(sQ + off, qp + (size_t)r * 3072 + c);
        cpa16(sK + off, kp + (size_t)r * 3072 + c);
        cpa16(sV + off, vp + (size_t)r * 3072 + c);
    }
    asm volatile("cp.async.commit_group;");

    uint32_t qf[4][4];
    float oa[8][4];
    float m0 = -1e30f, m1 = -1e30f, l0 = 0.f, l1 = 0.f;
#pragma unroll
    for (int i = 0; i < 8; i++) { oa[i][0] = oa[i][1] = oa[i][2] = oa[i][3] = 0.f; }

    for (int kt = 0; kt <= qt; kt++) {
        if (kt > 0) __syncthreads();
        if (kt < qt) {
            uint32_t st = (uint32_t)((kt + 1) & 1) * AT_TILEB;
#pragma unroll
            for (int i = 0; i < 4; i++) {
                int id = tid + (i << 7);
                int r = id >> 3, c = (id & 7) << 3;
                uint32_t off = (uint32_t)(r * AT_PAD + c) << 1;
                cpa16(sK + st + off, kp + (size_t)((kt + 1) * 64 + r) * 3072 + c);
                cpa16(sV + st + off, vp + (size_t)((kt + 1) * 64 + r) * 3072 + c);
            }
        }
        asm volatile("cp.async.commit_group;");
        asm volatile("cp.async.wait_group 1;");
        __syncthreads();

        if (kt == 0) {
            uint32_t rAq = (uint32_t)(wid << 4) + (lane & 7) + (((lane >> 3) & 1) << 3);
#pragma unroll
            for (int kc = 0; kc < 4; kc++) {
                uint32_t kAq = (((lane >> 4) & 1) << 3) + (kc << 4);
                ldsm4(qf[kc][0], qf[kc][1], qf[kc][2], qf[kc][3],
                      sQ + ((rAq * AT_PAD + kAq) << 1));
            }
        }

        uint32_t sKt = sK + (uint32_t)(kt & 1) * AT_TILEB;
        uint32_t sVt = sV + (uint32_t)(kt & 1) * AT_TILEB;

        float s[8][4];
#pragma unroll
        for (int i = 0; i < 8; i++) { s[i][0] = s[i][1] = s[i][2] = s[i][3] = 0.f; }
        uint32_t rBk = (lane & 7) + (((lane >> 4) & 1) << 3);
        uint32_t kBo = ((lane >> 3) & 1) << 3;
#pragma unroll
        for (int kc = 0; kc < 4; kc++) {
#pragma unroll
            for (int p = 0; p < 4; p++) {
                uint32_t b0, b1, b2, b3;
                ldsm4(b0, b1, b2, b3,
                      sKt + (((rBk + (uint32_t)(p << 4)) * AT_PAD + kBo + (kc << 4)) << 1));
                mma_f16(s[2*p][0], s[2*p][1], s[2*p][2], s[2*p][3],
                        qf[kc][0], qf[kc][1], qf[kc][2], qf[kc][3], b0, b1);
                mma_f16(s[2*p+1][0], s[2*p+1][1], s[2*p+1][2], s[2*p+1][3],
                        qf[kc][0], qf[kc][1], qf[kc][2], qf[kc][3], b2, b3);
            }
        }
#pragma unroll
        for (int i = 0; i < 8; i++) {
            s[i][0] *= 0.125f; s[i][1] *= 0.125f; s[i][2] *= 0.125f; s[i][3] *= 0.125f;
        }
        if (kt == qt) {
            int r0 = (wid << 4) + (lane >> 2);
#pragma unroll
            for (int nf = 0; nf < 8; nf++) {
                int c0 = (nf << 3) + ((lane & 3) << 1);
                if (c0     > r0)     s[nf][0] = -1e30f;
                if (c0 + 1 > r0)     s[nf][1] = -1e30f;
                if (c0     > r0 + 8) s[nf][2] = -1e30f;
                if (c0 + 1 > r0 + 8) s[nf][3] = -1e30f;
            }
        }

        float mx0 = s[0][0], mx1 = s[0][2];
#pragma unroll
        for (int nf = 0; nf < 8; nf++) {
            mx0 = fmaxf(mx0, fmaxf(s[nf][0], s[nf][1]));
            mx1 = fmaxf(mx1, fmaxf(s[nf][2], s[nf][3]));
        }
        mx0 = fmaxf(mx0, __shfl_xor_sync(0xffffffffu, mx0, 1));
        mx0 = fmaxf(mx0, __shfl_xor_sync(0xffffffffu, mx0, 2));
        mx1 = fmaxf(mx1, __shfl_xor_sync(0xffffffffu, mx1, 1));
        mx1 = fmaxf(mx1, __shfl_xor_sync(0xffffffffu, mx1, 2));
        float mn0 = fmaxf(m0, mx0), mn1 = fmaxf(m1, mx1);
        float cr0 = __expf(m0 - mn0), cr1 = __expf(m1 - mn1);
        float rs0 = 0.f, rs1 = 0.f;
        uint32_t pa[4][4];
#pragma unroll
        for (int nf = 0; nf < 8; nf++) {
            float p0 = __expf(s[nf][0] - mn0);
            float p1 = __expf(s[nf][1] - mn0);
            float p2 = __expf(s[nf][2] - mn1);
            float p3 = __expf(s[nf][3] - mn1);
            rs0 += p0 + p1; rs1 += p2 + p3;
            __half2 h01 = __floats2half2_rn(p0, p1);
            __half2 h23 = __floats2half2_rn(p2, p3);
            int kc = nf >> 1, hi = (nf & 1) << 1;
            pa[kc][hi]     = *(uint32_t*)&h01;
            pa[kc][hi + 1] = *(uint32_t*)&h23;
        }
        rs0 += __shfl_xor_sync(0xffffffffu, rs0, 1);
        rs0 += __shfl_xor_sync(0xffffffffu, rs0, 2);
        rs1 += __shfl_xor_sync(0xffffffffu, rs1, 1);
        rs1 += __shfl_xor_sync(0xffffffffu, rs1, 2);
        l0 = l0 * cr0 + rs0; l1 = l1 * cr1 + rs1;
        m0 = mn0; m1 = mn1;
#pragma unroll
        for (int i = 0; i < 8; i++) {
            oa[i][0] *= cr0; oa[i][1] *= cr0; oa[i][2] *= cr1; oa[i][3] *= cr1;
        }

        uint32_t rV = (lane & 7) + (((lane >> 3) & 1) << 3);
        uint32_t cV = ((lane >> 4) & 1) << 3;
#pragma unroll
        for (int kc = 0; kc < 4; kc++) {
#pragma unroll
            for (int p = 0; p < 4; p++) {
                uint32_t b0, b1, b2, b3;
                ldsm4t(b0, b1, b2, b3,
                       sVt + ((((uint32_t)(kc << 4) + rV) * AT_PAD + (uint32_t)(p << 4) + cV) << 1));
                mma_f16(oa[2*p][0], oa[2*p][1], oa[2*p][2], oa[2*p][3],
                        pa[kc][0], pa[kc][1], pa[kc][2], pa[kc][3], b0, b1);
                mma_f16(oa[2*p+1][0], oa[2*p+1][1], oa[2*p+1][2], oa[2*p+1][3],
                        pa[kc][0], pa[kc][1], pa[kc][2], pa[kc][3], b2, b3);
            }
        }
    }

    float i0 = 1.0f / l0, i1 = 1.0f / l1;
    int r0 = qt * 64 + (wid << 4) + (lane >> 2);
    __half* ob = outb + (size_t)(b * T_SEQ) * C_DIM + hh * 64;
#pragma unroll
    for (int nf = 0; nf < 8; nf++) {
        int c = (nf << 3) + ((lane & 3) << 1);
        __half2 h0 = __floats2half2_rn(oa[nf][0] * i0, oa[nf][1] * i0);
        __half2 h1 = __floats2half2_rn(oa[nf][2] * i1, oa[nf][3] * i1);
        *(__half2*)(ob + (size_t)r0 * C_DIM + c)       = h0;
        *(__half2*)(ob + (size_t)(r0 + 8) * C_DIM + c) = h1;
    }
}

// ---------------- smem sizes per instantiation (BK=64) ----------------
#define GSM_128_NK  ((128 * ROWH + 128 * ROWH) * 2 * 2)   // 73728
#define GSM_128_KN  ((128 * ROWH + 64 * ROWB) * 2 * 2)    // 71680
#define GSM_64_KN   ((64 * ROWH + 64 * ROWB) * 2 * 2)     // 53248

// ---------------- launcher ----------------
extern "C" void kernel_launch(void* const* d_in, const int* in_sizes, int n_in,
                              void* d_out, int out_size)
{
    const int*   idx    = (const int*)  d_in[0];
    const float* tok    = (const float*)d_in[1];
    const float* pos    = (const float*)d_in[2];
    const float* ln1_s  = (const float*)d_in[3];
    const float* ln1_b  = (const float*)d_in[4];
    const float* Wq     = (const float*)d_in[5];
    const float* Wk     = (const float*)d_in[6];
    const float* Wv     = (const float*)d_in[7];
    const float* Wo     = (const float*)d_in[8];
    const float* bo     = (const float*)d_in[9];
    const float* ln2_s  = (const float*)d_in[10];
    const float* ln2_b  = (const float*)d_in[11];
    const float* W1     = (const float*)d_in[12];
    const float* b1     = (const float*)d_in[13];
    const float* W2     = (const float*)d_in[14];
    const float* b2     = (const float*)d_in[15];
    const float* lnf_s  = (const float*)d_in[16];
    const float* lnf_b  = (const float*)d_in[17];
    float* out = (float*)d_out;

    float *x;
    __half *qkvh, *hh, *ffh, *wph, *woh, *w1h, *w2h, *tokh;
    cudaGetSymbolAddress((void**)&x,     g_x);
    cudaGetSymbolAddress((void**)&qkvh,  g_qkvh);
    cudaGetSymbolAddress((void**)&hh,    g_hh);
    cudaGetSymbolAddress((void**)&ffh,   g_ffh);
    cudaGetSymbolAddress((void**)&wph,   g_wph);
    cudaGetSymbolAddress((void**)&woh,   g_woh);
    cudaGetSymbolAddress((void**)&w1h,   g_w1h);
    cudaGetSymbolAddress((void**)&w2h,   g_w2h);
    cudaGetSymbolAddress((void**)&tokh,  g_tokh);

    cudaFuncSetAttribute(hgemm<128,1,1>, cudaFuncAttributeMaxDynamicSharedMemorySize, GSM_128_NK);
    cudaFuncSetAttribute(hgemm<128,0,1>, cudaFuncAttributeMaxDynamicSharedMemorySize, GSM_128_NK);
    cudaFuncSetAttribute(hgemm<128,1,0>, cudaFuncAttributeMaxDynamicSharedMemorySize, GSM_128_KN);
    cudaFuncSetAttribute(hgemm<64,0,0>,  cudaFuncAttributeMaxDynamicSharedMemorySize, GSM_64_KN);

    // ---- one-time per call: weight conversion ----
    k_cvt<<<(V_SZ * C_DIM) / 2048, 256>>>(tok, tokh);
    k_cvt<<<(L_NUM * C_DIM * C_DIM) / 2048, 256>>>(Wo, woh);
    k_cvt<<<(L_NUM * C_DIM * FF_DIM) / 2048, 256>>>(W1, w1h);
    k_cvt<<<(L_NUM * FF_DIM * C_DIM) / 2048, 256>>>(W2, w2h);
    k_packQKV<<<L_NUM * 1536, 256>>>(Wq, Wk, Wv, wph);
    k_embed<<<M_ROWS, 256>>>(idx, tok, pos, x);

    for (int l = 0; l < L_NUM; l++) {
        // LN1 -> half
        k_ln<<<M_ROWS, 256>>>(x, ln1_s + l * C_DIM, ln1_b + l * C_DIM, hh);
        // qkv = hh @ wph^T -> half
        hgemm<128,1,1><<<dim3(3072 / 128, M_ROWS / 128), 256, GSM_128_NK>>>(
            hh, wph + (size_t)l * 3 * C_DIM * C_DIM, qkvh, nullptr, nullptr, 3072, C_DIM, 0);
        // tensor-core flash attention -> hh
        k_attn<<<dim3(T_SEQ / 64, B_SZ * H_NUM), 128>>>(qkvh, hh);
        // x = x + hh @ Wo + bo   (Wo [K,N], MT=64)
        hgemm<64,0,0><<<dim3(C_DIM / 128, M_ROWS / 64), 256, GSM_64_KN>>>(
            hh, woh + (size_t)l * C_DIM * C_DIM, x, bo + l * C_DIM, x, C_DIM, C_DIM, 0);
        // LN2 -> half
        k_ln<<<M_ROWS, 256>>>(x, ln2_s + l * C_DIM, ln2_b + l * C_DIM, hh);
        // ffh = relu(hh @ W1 + b1) -> half  (W1 [K,N])
        hgemm<128,1,0><<<dim3(FF_DIM / 128, M_ROWS / 128), 256, GSM_128_KN>>>(
            hh, w1h + (size_t)l * C_DIM * FF_DIM, ffh, b1 + l * FF_DIM, nullptr, FF_DIM, C_DIM, 1);
        // x = x + ffh @ W2 + b2  (W2 [K,N], MT=64)
        hgemm<64,0,0><<<dim3(C_DIM / 128, M_ROWS / 64), 256, GSM_64_KN>>>(
            ffh, w2h + (size_t)l * FF_DIM * C_DIM, x, b2 + l * C_DIM, x, C_DIM, FF_DIM, 0);
    }

    // final LN + tied-embedding logits (tok [V,K] -> TRB=1)
    k_ln<<<M_ROWS, 256>>>(x, lnf_s, lnf_b, hh);
    hgemm<128,0,1><<<dim3(V_SZ / 128, M_ROWS / 128), 256, GSM_128_NK>>>(
        hh, tokh, out, nullptr, nullptr, V_SZ, C_DIM, 0);
}